// round 1
// baseline (speedup 1.0000x reference)
#include <cuda_runtime.h>
#include <cuda_bf16.h>
#include <cstdint>

// ---------------- problem constants ----------------
#define NM 20000
#define ND 8000
#define NE 200000
#define FIN 384
#define HD 512     // hidden
#define H1 512     // layer1 out
#define OD 256     // layer2 out

// ---------------- scratch (device globals, no allocation) ----------------
__device__ float g_xm[NM * HD];
__device__ float g_xd[ND * HD];
__device__ float g_aggm[NM * HD];
__device__ float g_aggd[ND * HD];
__device__ float g_hm[NM * H1];
__device__ float g_hd[ND * H1];
__device__ float g_um[NM * OD];
__device__ float g_ud[ND * OD];
__device__ int   g_cnt_m[NM];
__device__ int   g_cnt_d[ND];
__device__ int   g_off_m[NM + 1];
__device__ int   g_off_d[ND + 1];
__device__ int   g_cur_m[NM];
__device__ int   g_cur_d[ND];
__device__ int   g_csr_src[NE];  // edges grouped by disease dst -> stores mirna src
__device__ int   g_csr_dst[NE];  // edges grouped by mirna src  -> stores disease dst

// ---------------- SGEMM: C[M,N] = A[M,K] @ B[K,N] (+bias)(+D[idx[row]])(+C)(relu) ----
// 128x128 block tile, BK=8, 256 threads, 8x8 per thread (2x2 blocks of 4x4).
template <bool LOADC, bool BIAS, bool RELU, bool GATHERD>
__global__ __launch_bounds__(256) void sgemm_kernel(
    const float* __restrict__ A, const float* __restrict__ B,
    float* __restrict__ C, const float* __restrict__ bias,
    const float* __restrict__ Dm, const int* __restrict__ idx,
    int M, int N, int K)
{
    __shared__ float As[8][128];
    __shared__ float Bs[8][128];

    const int bm = blockIdx.y * 128;
    const int bn = blockIdx.x * 128;
    const int tid = threadIdx.x;

    // global load mapping
    const int arow = tid >> 1;            // 0..127
    const int acol = (tid & 1) * 4;       // 0 or 4
    const int brow = tid >> 5;            // 0..7
    const int bcol = (tid & 31) * 4;      // 0..124

    // compute mapping
    const int tr = (tid >> 4) * 4;        // 0..60 (row strip base; +64 second strip)
    const int tc = (tid & 15) * 4;        // 0..60 (col strip base; +64 second strip)

    const bool arow_ok = (bm + arow) < M;

    float acc[2][2][4][4];
#pragma unroll
    for (int i = 0; i < 2; i++)
#pragma unroll
        for (int j = 0; j < 2; j++)
#pragma unroll
            for (int r = 0; r < 4; r++)
#pragma unroll
                for (int c = 0; c < 4; c++)
                    acc[i][j][r][c] = 0.0f;

    for (int k0 = 0; k0 < K; k0 += 8) {
        float4 av = make_float4(0.f, 0.f, 0.f, 0.f);
        if (arow_ok)
            av = *(const float4*)(A + (size_t)(bm + arow) * K + k0 + acol);
        As[acol + 0][arow] = av.x;
        As[acol + 1][arow] = av.y;
        As[acol + 2][arow] = av.z;
        As[acol + 3][arow] = av.w;

        float4 bv = *(const float4*)(B + (size_t)(k0 + brow) * N + bn + bcol);
        *(float4*)&Bs[brow][bcol] = bv;

        __syncthreads();

#pragma unroll
        for (int kk = 0; kk < 8; kk++) {
            float4 a0 = *(float4*)&As[kk][tr];
            float4 a1 = *(float4*)&As[kk][tr + 64];
            float4 b0 = *(float4*)&Bs[kk][tc];
            float4 b1 = *(float4*)&Bs[kk][tc + 64];
            float ar[2][4] = {{a0.x, a0.y, a0.z, a0.w}, {a1.x, a1.y, a1.z, a1.w}};
            float br[2][4] = {{b0.x, b0.y, b0.z, b0.w}, {b1.x, b1.y, b1.z, b1.w}};
#pragma unroll
            for (int ri = 0; ri < 2; ri++)
#pragma unroll
                for (int ci = 0; ci < 2; ci++)
#pragma unroll
                    for (int r = 0; r < 4; r++)
#pragma unroll
                        for (int c = 0; c < 4; c++)
                            acc[ri][ci][r][c] = fmaf(ar[ri][r], br[ci][c], acc[ri][ci][r][c]);
        }
        __syncthreads();
    }

    // epilogue
#pragma unroll
    for (int ri = 0; ri < 2; ri++) {
#pragma unroll
        for (int r = 0; r < 4; r++) {
            int row = bm + tr + ri * 64 + r;
            if (row >= M) continue;
            int grow = row;
            if (GATHERD && idx) grow = idx[row];
#pragma unroll
            for (int ci = 0; ci < 2; ci++) {
                int col = bn + tc + ci * 64;
                float4 v = make_float4(acc[ri][ci][r][0], acc[ri][ci][r][1],
                                       acc[ri][ci][r][2], acc[ri][ci][r][3]);
                if (BIAS) {
                    float4 b = *(const float4*)(bias + col);
                    v.x += b.x; v.y += b.y; v.z += b.z; v.w += b.w;
                }
                if (GATHERD) {
                    float4 d = *(const float4*)(Dm + (size_t)grow * N + col);
                    v.x += d.x; v.y += d.y; v.z += d.z; v.w += d.w;
                }
                float* cptr = C + (size_t)row * N + col;
                if (LOADC) {
                    float4 o = *(const float4*)cptr;
                    v.x += o.x; v.y += o.y; v.z += o.z; v.w += o.w;
                }
                if (RELU) {
                    v.x = fmaxf(v.x, 0.f); v.y = fmaxf(v.y, 0.f);
                    v.z = fmaxf(v.z, 0.f); v.w = fmaxf(v.w, 0.f);
                }
                *(float4*)cptr = v;
            }
        }
    }
}

// ---------------- CSR build ----------------
__global__ void count_edges_kernel(const int* __restrict__ src, const int* __restrict__ dst,
                                   int* __restrict__ cm, int* __restrict__ cd, int E)
{
    int i = blockIdx.x * blockDim.x + threadIdx.x;
    if (i < E) {
        atomicAdd(&cd[dst[i]], 1);
        atomicAdd(&cm[src[i]], 1);
    }
}

__global__ void exscan_kernel(const int* __restrict__ cnt, int* __restrict__ off, int n)
{
    __shared__ int sm[1024];
    __shared__ int carry_s;
    int t = threadIdx.x;
    if (t == 0) carry_s = 0;
    __syncthreads();
    for (int base = 0; base < n; base += 1024) {
        int i = base + t;
        int v = (i < n) ? cnt[i] : 0;
        sm[t] = v;
        __syncthreads();
        for (int d = 1; d < 1024; d <<= 1) {
            int add = (t >= d) ? sm[t - d] : 0;
            __syncthreads();
            sm[t] += add;
            __syncthreads();
        }
        int carry = carry_s;
        if (i < n) off[i] = carry + sm[t] - v;
        __syncthreads();
        if (t == 1023) carry_s = carry + sm[1023];
        __syncthreads();
    }
    if (t == 0) off[n] = carry_s;
}

__global__ void fill_csr_kernel(const int* __restrict__ src, const int* __restrict__ dst,
                                int* __restrict__ cur_m, int* __restrict__ cur_d,
                                int* __restrict__ csr_src, int* __restrict__ csr_dst, int E)
{
    int i = blockIdx.x * blockDim.x + threadIdx.x;
    if (i < E) {
        int m = src[i], d = dst[i];
        int p = atomicAdd(&cur_d[d], 1);
        csr_src[p] = m;
        int q = atomicAdd(&cur_m[m], 1);
        csr_dst[q] = d;
    }
}

// ---------------- segment mean (gather, no atomics) ----------------
// one block per destination row; WIDTH/4 threads, each owns one float4 column chunk
template <int WIDTH, bool ACCUM>
__global__ void seg_mean_kernel(const float* __restrict__ X, const int* __restrict__ off,
                                const int* __restrict__ nbr, float* __restrict__ C)
{
    int row = blockIdx.x;
    int t = threadIdx.x;
    int s = off[row], e = off[row + 1];
    float4 acc = make_float4(0.f, 0.f, 0.f, 0.f);
    for (int i = s; i < e; i++) {
        int nb = __ldg(&nbr[i]);
        float4 v = __ldg((const float4*)(X + (size_t)nb * WIDTH) + t);
        acc.x += v.x; acc.y += v.y; acc.z += v.z; acc.w += v.w;
    }
    float inv = (e > s) ? 1.0f / (float)(e - s) : 0.0f;
    acc.x *= inv; acc.y *= inv; acc.z *= inv; acc.w *= inv;
    float4* cp = (float4*)(C + (size_t)row * WIDTH) + t;
    if (ACCUM) {
        float4 o = *cp;
        acc.x += o.x; acc.y += o.y; acc.z += o.z; acc.w += o.w;
    }
    *cp = acc;
}

// ---------------- host orchestration ----------------
static inline dim3 gemm_grid(int M, int N) { return dim3((N + 127) / 128, (M + 127) / 128); }

extern "C" void kernel_launch(void* const* d_in, const int* in_sizes, int n_in,
                              void* d_out, int out_size)
{
    const float* mf   = (const float*)d_in[0];
    const float* df   = (const float*)d_in[1];
    const int*   mid  = (const int*)d_in[2];
    const int*   did  = (const int*)d_in[3];
    const int*   esrc = (const int*)d_in[4];
    const int*   edst = (const int*)d_in[5];
    const float* Wm   = (const float*)d_in[6];
    const float* bm   = (const float*)d_in[7];
    const float* Wd   = (const float*)d_in[8];
    const float* bd   = (const float*)d_in[9];
    const float* memb = (const float*)d_in[10];
    const float* demb = (const float*)d_in[11];
    const float* W1mdl = (const float*)d_in[12];
    const float* b1md  = (const float*)d_in[13];
    const float* W1mdr = (const float*)d_in[14];
    const float* W1dml = (const float*)d_in[15];
    const float* b1dm  = (const float*)d_in[16];
    const float* W1dmr = (const float*)d_in[17];
    const float* W2mdl = (const float*)d_in[18];
    const float* b2md  = (const float*)d_in[19];
    const float* W2mdr = (const float*)d_in[20];
    const float* W2dml = (const float*)d_in[21];
    const float* b2dm  = (const float*)d_in[22];
    const float* W2dmr = (const float*)d_in[23];

    float* out = (float*)d_out;
    float* o_m = out;                 // [NM, OD]
    float* o_d = out + (size_t)NM * OD; // [ND, OD]

    float *xm, *xd, *aggm, *aggd, *hm, *hd, *um, *ud;
    int *cnt_m, *cnt_d, *off_m, *off_d, *cur_m, *cur_d, *csr_src, *csr_dst;
    cudaGetSymbolAddress((void**)&xm, g_xm);
    cudaGetSymbolAddress((void**)&xd, g_xd);
    cudaGetSymbolAddress((void**)&aggm, g_aggm);
    cudaGetSymbolAddress((void**)&aggd, g_aggd);
    cudaGetSymbolAddress((void**)&hm, g_hm);
    cudaGetSymbolAddress((void**)&hd, g_hd);
    cudaGetSymbolAddress((void**)&um, g_um);
    cudaGetSymbolAddress((void**)&ud, g_ud);
    cudaGetSymbolAddress((void**)&cnt_m, g_cnt_m);
    cudaGetSymbolAddress((void**)&cnt_d, g_cnt_d);
    cudaGetSymbolAddress((void**)&off_m, g_off_m);
    cudaGetSymbolAddress((void**)&off_d, g_off_d);
    cudaGetSymbolAddress((void**)&cur_m, g_cur_m);
    cudaGetSymbolAddress((void**)&cur_d, g_cur_d);
    cudaGetSymbolAddress((void**)&csr_src, g_csr_src);
    cudaGetSymbolAddress((void**)&csr_dst, g_csr_dst);

    // 1) input encoders: x = feat @ W + b + emb[node_id]
    sgemm_kernel<false, true, false, true><<<gemm_grid(NM, HD), 256>>>(
        mf, Wm, xm, bm, memb, mid, NM, HD, FIN);
    sgemm_kernel<false, true, false, true><<<gemm_grid(ND, HD), 256>>>(
        df, Wd, xd, bd, demb, did, ND, HD, FIN);

    // 2) CSR build (both directions)
    cudaMemsetAsync(cnt_m, 0, NM * sizeof(int), 0);
    cudaMemsetAsync(cnt_d, 0, ND * sizeof(int), 0);
    count_edges_kernel<<<(NE + 255) / 256, 256>>>(esrc, edst, cnt_m, cnt_d, NE);
    exscan_kernel<<<1, 1024>>>(cnt_d, off_d, ND);
    exscan_kernel<<<1, 1024>>>(cnt_m, off_m, NM);
    cudaMemcpyAsync(cur_d, off_d, ND * sizeof(int), cudaMemcpyDeviceToDevice, 0);
    cudaMemcpyAsync(cur_m, off_m, NM * sizeof(int), cudaMemcpyDeviceToDevice, 0);
    fill_csr_kernel<<<(NE + 255) / 256, 256>>>(esrc, edst, cur_m, cur_d, csr_src, csr_dst, NE);

    // 3) layer 1: segment means then SAGE GEMMs (relu)
    seg_mean_kernel<HD, false><<<ND, HD / 4>>>(xm, off_d, csr_src, aggd);
    seg_mean_kernel<HD, false><<<NM, HD / 4>>>(xd, off_m, csr_dst, aggm);

    // h_d = relu(aggd @ W1_md_l + b1_md + x_d @ W1_md_r)
    sgemm_kernel<false, false, false, false><<<gemm_grid(ND, H1), 256>>>(
        xd, W1mdr, hd, nullptr, nullptr, nullptr, ND, H1, HD);
    sgemm_kernel<true, true, true, false><<<gemm_grid(ND, H1), 256>>>(
        aggd, W1mdl, hd, b1md, nullptr, nullptr, ND, H1, HD);
    // h_m = relu(aggm @ W1_dm_l + b1_dm + x_m @ W1_dm_r)
    sgemm_kernel<false, false, false, false><<<gemm_grid(NM, H1), 256>>>(
        xm, W1dmr, hm, nullptr, nullptr, nullptr, NM, H1, HD);
    sgemm_kernel<true, true, true, false><<<gemm_grid(NM, H1), 256>>>(
        aggm, W1dml, hm, b1dm, nullptr, nullptr, NM, H1, HD);

    // 4) layer 2: GEMM first, aggregate after (mean commutes with linear map)
    sgemm_kernel<false, false, false, false><<<gemm_grid(NM, OD), 256>>>(
        hm, W2mdl, um, nullptr, nullptr, nullptr, NM, OD, H1);
    sgemm_kernel<false, false, false, false><<<gemm_grid(ND, OD), 256>>>(
        hd, W2dml, ud, nullptr, nullptr, nullptr, ND, OD, H1);
    // bases: o = h_dst @ Wr + b
    sgemm_kernel<false, true, false, false><<<gemm_grid(ND, OD), 256>>>(
        hd, W2mdr, o_d, b2md, nullptr, nullptr, ND, OD, H1);
    sgemm_kernel<false, true, false, false><<<gemm_grid(NM, OD), 256>>>(
        hm, W2dmr, o_m, b2dm, nullptr, nullptr, NM, OD, H1);
    // accumulate segment means of projected messages into outputs
    seg_mean_kernel<OD, true><<<ND, OD / 4>>>(um, off_d, csr_src, o_d);
    seg_mean_kernel<OD, true><<<NM, OD / 4>>>(ud, off_m, csr_dst, o_m);
}

// round 2
// speedup vs baseline: 2.2402x; 2.2402x over previous
#include <cuda_runtime.h>
#include <cuda_bf16.h>
#include <cstdint>

#define NM 20000
#define ND 8000
#define NE 200000
#define FIN 384
#define HD 512
#define H1 512
#define OD 256

typedef __nv_bfloat16 bf16;
typedef __nv_bfloat162 bf162;

// ---------------- scratch (device globals) ----------------
__device__ bf16 g_mfh[NM*FIN], g_mfl[NM*FIN];
__device__ bf16 g_dfh[ND*FIN], g_dfl[ND*FIN];
__device__ bf16 g_xmh[NM*HD],  g_xml[NM*HD];
__device__ bf16 g_xdh[ND*HD],  g_xdl[ND*HD];
__device__ bf16 g_amh[NM*HD],  g_aml[NM*HD];
__device__ bf16 g_adh[ND*HD],  g_adl[ND*HD];
__device__ bf16 g_hmh[NM*H1],  g_hml[NM*H1];
__device__ bf16 g_hdh[ND*H1],  g_hdl[ND*H1];
__device__ float g_um[NM*OD];
__device__ float g_ud[ND*OD];
__device__ bf16 g_wmh[FIN*HD], g_wml[FIN*HD];
__device__ bf16 g_wdh[FIN*HD], g_wdl[FIN*HD];
__device__ bf16 g_w1mdlh[HD*H1], g_w1mdll[HD*H1];
__device__ bf16 g_w1mdrh[HD*H1], g_w1mdrl[HD*H1];
__device__ bf16 g_w1dmlh[HD*H1], g_w1dmll[HD*H1];
__device__ bf16 g_w1dmrh[HD*H1], g_w1dmrl[HD*H1];
__device__ bf16 g_w2mdlh[H1*OD], g_w2mdll[H1*OD];
__device__ bf16 g_w2mdrh[H1*OD], g_w2mdrl[H1*OD];
__device__ bf16 g_w2dmlh[H1*OD], g_w2dmll[H1*OD];
__device__ bf16 g_w2dmrh[H1*OD], g_w2dmrl[H1*OD];
__device__ int g_cnt_m[NM], g_cnt_d[ND];
__device__ int g_off_m[NM+1], g_off_d[ND+1];
__device__ int g_cur_m[NM], g_cur_d[ND];
__device__ int g_csr_src[NE], g_csr_dst[NE];

// ---------------- PTX helpers ----------------
__device__ __forceinline__ void ldsm_x4(uint32_t& r0,uint32_t& r1,uint32_t& r2,uint32_t& r3,uint32_t a){
    asm volatile("ldmatrix.sync.aligned.m8n8.x4.shared.b16 {%0,%1,%2,%3},[%4];"
                 :"=r"(r0),"=r"(r1),"=r"(r2),"=r"(r3):"r"(a));
}
__device__ __forceinline__ void ldsm_x4t(uint32_t& r0,uint32_t& r1,uint32_t& r2,uint32_t& r3,uint32_t a){
    asm volatile("ldmatrix.sync.aligned.m8n8.x4.trans.shared.b16 {%0,%1,%2,%3},[%4];"
                 :"=r"(r0),"=r"(r1),"=r"(r2),"=r"(r3):"r"(a));
}
__device__ __forceinline__ void mma_bf16(float* c, const uint32_t* a, uint32_t b0, uint32_t b1){
    asm volatile("mma.sync.aligned.m16n8k16.row.col.f32.bf16.bf16.f32 "
        "{%0,%1,%2,%3},{%4,%5,%6,%7},{%8,%9},{%0,%1,%2,%3};"
        :"+f"(c[0]),"+f"(c[1]),"+f"(c[2]),"+f"(c[3])
        :"r"(a[0]),"r"(a[1]),"r"(a[2]),"r"(a[3]),"r"(b0),"r"(b1));
}
__device__ __forceinline__ void cpa16(uint32_t d, const void* s, bool p){
    int sz = p ? 16 : 0;
    asm volatile("cp.async.cg.shared.global [%0],[%1],16,%2;"::"r"(d),"l"(s),"r"(sz));
}

// smem geometry (bf16 elements)
#define SA 40          // A row stride (32 + 8 pad) -> 80B, conflict-free LDSM
#define SB 136         // B row stride (128 + 8 pad) -> 272B, conflict-free LDSM
#define ASZ (128*SA)   // 5120
#define BSZ (32*SB)    // 4352
#define STAGE_E (2*ASZ + 2*BSZ)      // 18944 elems
#define GEMM_SMEM_BYTES (2*STAGE_E*2) // 75776 bytes

// ---------------- bf16x3 tensor-core GEMM ----------------
// C[M,N] = sum over (A1@B1)(+A2@B2) with A = Ah+Al, B = Bh+Bl (3-term compensated)
// epilogue: +bias, +Demb[idx[row]], relu, write f32 or split hi/lo bf16
template<bool BIAS,bool RELU,bool GATH,bool SPLIT>
__global__ __launch_bounds__(256,2) void mma_gemm(
    const bf16* __restrict__ A1h, const bf16* __restrict__ A1l,
    const bf16* __restrict__ B1h, const bf16* __restrict__ B1l, int K1,
    const bf16* __restrict__ A2h, const bf16* __restrict__ A2l,
    const bf16* __restrict__ B2h, const bf16* __restrict__ B2l, int K2,
    int M, int N,
    const float* __restrict__ bias, const float* __restrict__ Demb, const int* __restrict__ idx,
    float* __restrict__ C, bf16* __restrict__ Ch, bf16* __restrict__ Cl)
{
    extern __shared__ bf16 smem[];
    uint32_t sbase = (uint32_t)__cvta_generic_to_shared(smem);
    const int tid  = threadIdx.x;
    const int lane = tid & 31;
    const int wid  = tid >> 5;
    const int wm   = (wid & 3) * 32;
    const int wn   = (wid >> 2) * 64;
    const int bm   = blockIdx.y * 128;
    const int bn   = blockIdx.x * 128;
    const int S1 = K1 >> 5, S2 = K2 >> 5, S = S1 + S2;

    float acc[2][8][4];
#pragma unroll
    for (int i=0;i<2;i++)
#pragma unroll
        for (int j=0;j<8;j++)
#pragma unroll
            for (int k=0;k<4;k++) acc[i][j][k] = 0.f;

    auto prefetch = [&](int s){
        const bf16 *Ah,*Al,*Bh,*Bl; int K,k0;
        if (s < S1){ Ah=A1h; Al=A1l; Bh=B1h; Bl=B1l; K=K1; k0=s<<5; }
        else       { Ah=A2h; Al=A2l; Bh=B2h; Bl=B2l; K=K2; k0=(s-S1)<<5; }
        uint32_t sb = sbase + (uint32_t)((s&1)*STAGE_E*2);
        int ar = tid>>2, ac = (tid&3)*8;
#pragma unroll
        for (int i=0;i<2;i++){
            int row = bm + ar + 64*i;
            bool ok = row < M;
            int sr = ok ? row : 0;
            uint32_t d = sb + (uint32_t)(((ar+64*i)*SA + ac)*2);
            cpa16(d,          Ah + (size_t)sr*K + k0 + ac, ok);
            cpa16(d + ASZ*2,  Al + (size_t)sr*K + k0 + ac, ok);
        }
        int bk = tid>>4, bc = (tid&15)*8;
#pragma unroll
        for (int i=0;i<2;i++){
            int k = bk + 16*i;
            uint32_t d = sb + (uint32_t)((2*ASZ + k*SB + bc)*2);
            size_t go = (size_t)(k0+k)*N + bn + bc;
            cpa16(d,          Bh + go, true);
            cpa16(d + BSZ*2,  Bl + go, true);
        }
        asm volatile("cp.async.commit_group;");
    };

    prefetch(0);
    for (int s=0;s<S;s++){
        if (s+1 < S){
            prefetch(s+1);
            asm volatile("cp.async.wait_group 1;");
        } else {
            asm volatile("cp.async.wait_group 0;");
        }
        __syncthreads();
        uint32_t sb = sbase + (uint32_t)((s&1)*STAGE_E*2);
#pragma unroll
        for (int kk=0;kk<2;kk++){
            const int k16 = kk*16;
            const int loff = (lane>>1)&8;   // (lane&16)?8:0
            uint32_t ah[2][4], al[2][4];
#pragma unroll
            for (int mf=0;mf<2;mf++){
                uint32_t a = sb + (uint32_t)((((wm + mf*16 + (lane&15))*SA) + k16 + loff)*2);
                ldsm_x4(ah[mf][0],ah[mf][1],ah[mf][2],ah[mf][3], a);
                ldsm_x4(al[mf][0],al[mf][1],al[mf][2],al[mf][3], a + ASZ*2);
            }
#pragma unroll
            for (int nb=0;nb<4;nb++){
                uint32_t a = sb + (uint32_t)((2*ASZ + (k16 + (lane&15))*SB + wn + nb*16 + loff)*2);
                uint32_t bh[4], bl[4];
                ldsm_x4t(bh[0],bh[1],bh[2],bh[3], a);
                ldsm_x4t(bl[0],bl[1],bl[2],bl[3], a + BSZ*2);
#pragma unroll
                for (int h=0;h<2;h++){
#pragma unroll
                    for (int mf=0;mf<2;mf++){
                        float* c = acc[mf][nb*2+h];
                        mma_bf16(c, ah[mf], bh[2*h], bh[2*h+1]);  // hi*hi
                        mma_bf16(c, ah[mf], bl[2*h], bl[2*h+1]);  // hi*lo
                        mma_bf16(c, al[mf], bh[2*h], bh[2*h+1]);  // lo*hi
                    }
                }
            }
        }
        __syncthreads();
    }

    // epilogue
#pragma unroll
    for (int mf=0;mf<2;mf++){
#pragma unroll
        for (int nf=0;nf<8;nf++){
            int col = bn + wn + nf*8 + (lane&3)*2;
#pragma unroll
            for (int half=0;half<2;half++){
                int row = bm + wm + mf*16 + (lane>>2) + half*8;
                if (row >= M) continue;
                float v0 = acc[mf][nf][half*2+0];
                float v1 = acc[mf][nf][half*2+1];
                if (BIAS){ v0 += __ldg(&bias[col]); v1 += __ldg(&bias[col+1]); }
                if (GATH){
                    int g = __ldg(&idx[row]);
                    const float* e = Demb + (size_t)g*N + col;
                    v0 += __ldg(&e[0]); v1 += __ldg(&e[1]);
                }
                if (RELU){ v0 = fmaxf(v0,0.f); v1 = fmaxf(v1,0.f); }
                if (SPLIT){
                    bf16 h0=__float2bfloat16(v0), h1=__float2bfloat16(v1);
                    bf16 l0=__float2bfloat16(v0-__bfloat162float(h0));
                    bf16 l1=__float2bfloat16(v1-__bfloat162float(h1));
                    *(bf162*)(Ch + (size_t)row*N + col) = __halves2bfloat162(h0,h1);
                    *(bf162*)(Cl + (size_t)row*N + col) = __halves2bfloat162(l0,l1);
                } else {
                    float2 o; o.x=v0; o.y=v1;
                    *(float2*)(C + (size_t)row*N + col) = o;
                }
            }
        }
    }
}

// ---------------- split fp32 -> (bf16 hi, bf16 lo) ----------------
__global__ void split_kernel(const float* __restrict__ X, bf16* __restrict__ H,
                             bf16* __restrict__ L, int n4)
{
    int i = blockIdx.x*blockDim.x + threadIdx.x;
    if (i < n4){
        float4 v = ((const float4*)X)[i];
        bf16 h0=__float2bfloat16(v.x), h1=__float2bfloat16(v.y);
        bf16 h2=__float2bfloat16(v.z), h3=__float2bfloat16(v.w);
        bf16 l0=__float2bfloat16(v.x-__bfloat162float(h0));
        bf16 l1=__float2bfloat16(v.y-__bfloat162float(h1));
        bf16 l2=__float2bfloat16(v.z-__bfloat162float(h2));
        bf16 l3=__float2bfloat16(v.w-__bfloat162float(h3));
        ((bf162*)H)[2*i]   = __halves2bfloat162(h0,h1);
        ((bf162*)H)[2*i+1] = __halves2bfloat162(h2,h3);
        ((bf162*)L)[2*i]   = __halves2bfloat162(l0,l1);
        ((bf162*)L)[2*i+1] = __halves2bfloat162(l2,l3);
    }
}

// ---------------- CSR build ----------------
__global__ void count_edges_kernel(const int* __restrict__ src, const int* __restrict__ dst,
                                   int* __restrict__ cm, int* __restrict__ cd, int E)
{
    int i = blockIdx.x * blockDim.x + threadIdx.x;
    if (i < E) {
        atomicAdd(&cd[dst[i]], 1);
        atomicAdd(&cm[src[i]], 1);
    }
}

__global__ void exscan_kernel(const int* __restrict__ cnt, int* __restrict__ off, int n)
{
    __shared__ int sm[1024];
    __shared__ int carry_s;
    int t = threadIdx.x;
    if (t == 0) carry_s = 0;
    __syncthreads();
    for (int base = 0; base < n; base += 1024) {
        int i = base + t;
        int v = (i < n) ? cnt[i] : 0;
        sm[t] = v;
        __syncthreads();
        for (int d = 1; d < 1024; d <<= 1) {
            int add = (t >= d) ? sm[t - d] : 0;
            __syncthreads();
            sm[t] += add;
            __syncthreads();
        }
        int carry = carry_s;
        if (i < n) off[i] = carry + sm[t] - v;
        __syncthreads();
        if (t == 1023) carry_s = carry + sm[1023];
        __syncthreads();
    }
    if (t == 0) off[n] = carry_s;
}

__global__ void fill_csr_kernel(const int* __restrict__ src, const int* __restrict__ dst,
                                int* __restrict__ cur_m, int* __restrict__ cur_d,
                                int* __restrict__ csr_src, int* __restrict__ csr_dst, int E)
{
    int i = blockIdx.x * blockDim.x + threadIdx.x;
    if (i < E) {
        int m = src[i], d = dst[i];
        int p = atomicAdd(&cur_d[d], 1);
        csr_src[p] = m;
        int q = atomicAdd(&cur_m[m], 1);
        csr_dst[q] = d;
    }
}

// ---------------- segment mean: split-in -> split-out ----------------
template<int WIDTH>
__global__ void seg_mean_split_kernel(const bf16* __restrict__ Xh, const bf16* __restrict__ Xl,
                                      const int* __restrict__ off, const int* __restrict__ nbr,
                                      bf16* __restrict__ Ch, bf16* __restrict__ Cl)
{
    int row = blockIdx.x;
    int t = threadIdx.x;  // WIDTH/4 threads, 4 cols each
    int s = off[row], e = off[row + 1];
    float a0=0.f,a1=0.f,a2=0.f,a3=0.f;
    for (int i = s; i < e; i++){
        int nb = __ldg(&nbr[i]);
        const bf162* ph = (const bf162*)(Xh + (size_t)nb*WIDTH);
        const bf162* pl = (const bf162*)(Xl + (size_t)nb*WIDTH);
        bf162 h0 = __ldg(&ph[2*t]), h1 = __ldg(&ph[2*t+1]);
        bf162 l0 = __ldg(&pl[2*t]), l1 = __ldg(&pl[2*t+1]);
        a0 += __bfloat162float(h0.x) + __bfloat162float(l0.x);
        a1 += __bfloat162float(h0.y) + __bfloat162float(l0.y);
        a2 += __bfloat162float(h1.x) + __bfloat162float(l1.x);
        a3 += __bfloat162float(h1.y) + __bfloat162float(l1.y);
    }
    float inv = (e > s) ? 1.0f/(float)(e - s) : 0.0f;
    a0 *= inv; a1 *= inv; a2 *= inv; a3 *= inv;
    bf16 h0=__float2bfloat16(a0), h1=__float2bfloat16(a1);
    bf16 h2=__float2bfloat16(a2), h3=__float2bfloat16(a3);
    bf16 l0=__float2bfloat16(a0-__bfloat162float(h0));
    bf16 l1=__float2bfloat16(a1-__bfloat162float(h1));
    bf16 l2=__float2bfloat16(a2-__bfloat162float(h2));
    bf16 l3=__float2bfloat16(a3-__bfloat162float(h3));
    bf162* och = (bf162*)(Ch + (size_t)row*WIDTH);
    bf162* ocl = (bf162*)(Cl + (size_t)row*WIDTH);
    och[2*t]   = __halves2bfloat162(h0,h1);
    och[2*t+1] = __halves2bfloat162(h2,h3);
    ocl[2*t]   = __halves2bfloat162(l0,l1);
    ocl[2*t+1] = __halves2bfloat162(l2,l3);
}

// ---------------- segment mean: f32-in, accumulate into f32 out ----------------
template <int WIDTH>
__global__ void seg_mean_acc_kernel(const float* __restrict__ X, const int* __restrict__ off,
                                    const int* __restrict__ nbr, float* __restrict__ C)
{
    int row = blockIdx.x;
    int t = threadIdx.x;  // WIDTH/4
    int s = off[row], e = off[row + 1];
    float4 acc = make_float4(0.f, 0.f, 0.f, 0.f);
    for (int i = s; i < e; i++) {
        int nb = __ldg(&nbr[i]);
        float4 v = __ldg((const float4*)(X + (size_t)nb * WIDTH) + t);
        acc.x += v.x; acc.y += v.y; acc.z += v.z; acc.w += v.w;
    }
    float inv = (e > s) ? 1.0f / (float)(e - s) : 0.0f;
    float4* cp = (float4*)(C + (size_t)row * WIDTH) + t;
    float4 o = *cp;
    o.x += acc.x*inv; o.y += acc.y*inv; o.z += acc.z*inv; o.w += acc.w*inv;
    *cp = o;
}

// ---------------- host orchestration ----------------
static inline dim3 gemm_grid(int M, int N) { return dim3(N / 128, (M + 127) / 128); }
#define SYM(p, s) cudaGetSymbolAddress((void**)&(p), s)

extern "C" void kernel_launch(void* const* d_in, const int* in_sizes, int n_in,
                              void* d_out, int out_size)
{
    const float* mf   = (const float*)d_in[0];
    const float* df   = (const float*)d_in[1];
    const int*   mid  = (const int*)d_in[2];
    const int*   did  = (const int*)d_in[3];
    const int*   esrc = (const int*)d_in[4];
    const int*   edst = (const int*)d_in[5];
    const float* Wm   = (const float*)d_in[6];
    const float* bm   = (const float*)d_in[7];
    const float* Wd   = (const float*)d_in[8];
    const float* bd   = (const float*)d_in[9];
    const float* memb = (const float*)d_in[10];
    const float* demb = (const float*)d_in[11];
    const float* W1mdl = (const float*)d_in[12];
    const float* b1md  = (const float*)d_in[13];
    const float* W1mdr = (const float*)d_in[14];
    const float* W1dml = (const float*)d_in[15];
    const float* b1dm  = (const float*)d_in[16];
    const float* W1dmr = (const float*)d_in[17];
    const float* W2mdl = (const float*)d_in[18];
    const float* b2md  = (const float*)d_in[19];
    const float* W2mdr = (const float*)d_in[20];
    const float* W2dml = (const float*)d_in[21];
    const float* b2dm  = (const float*)d_in[22];
    const float* W2dmr = (const float*)d_in[23];

    float* out = (float*)d_out;
    float* o_m = out;                    // [NM, OD]
    float* o_d = out + (size_t)NM * OD;  // [ND, OD]

    bf16 *mfh,*mfl,*dfh,*dfl,*xmh,*xml,*xdh,*xdl,*amh,*aml,*adh,*adl,*hmh,*hml,*hdh,*hdl;
    bf16 *wmh,*wml,*wdh,*wdl;
    bf16 *w1mdlh,*w1mdll,*w1mdrh,*w1mdrl,*w1dmlh,*w1dmll,*w1dmrh,*w1dmrl;
    bf16 *w2mdlh,*w2mdll,*w2mdrh,*w2mdrl,*w2dmlh,*w2dmll,*w2dmrh,*w2dmrl;
    float *um,*ud;
    int *cnt_m,*cnt_d,*off_m,*off_d,*cur_m,*cur_d,*csr_src,*csr_dst;
    SYM(mfh,g_mfh); SYM(mfl,g_mfl); SYM(dfh,g_dfh); SYM(dfl,g_dfl);
    SYM(xmh,g_xmh); SYM(xml,g_xml); SYM(xdh,g_xdh); SYM(xdl,g_xdl);
    SYM(amh,g_amh); SYM(aml,g_aml); SYM(adh,g_adh); SYM(adl,g_adl);
    SYM(hmh,g_hmh); SYM(hml,g_hml); SYM(hdh,g_hdh); SYM(hdl,g_hdl);
    SYM(wmh,g_wmh); SYM(wml,g_wml); SYM(wdh,g_wdh); SYM(wdl,g_wdl);
    SYM(w1mdlh,g_w1mdlh); SYM(w1mdll,g_w1mdll); SYM(w1mdrh,g_w1mdrh); SYM(w1mdrl,g_w1mdrl);
    SYM(w1dmlh,g_w1dmlh); SYM(w1dmll,g_w1dmll); SYM(w1dmrh,g_w1dmrh); SYM(w1dmrl,g_w1dmrl);
    SYM(w2mdlh,g_w2mdlh); SYM(w2mdll,g_w2mdll); SYM(w2mdrh,g_w2mdrh); SYM(w2mdrl,g_w2mdrl);
    SYM(w2dmlh,g_w2dmlh); SYM(w2dmll,g_w2dmll); SYM(w2dmrh,g_w2dmrh); SYM(w2dmrl,g_w2dmrl);
    SYM(um,g_um); SYM(ud,g_ud);
    SYM(cnt_m,g_cnt_m); SYM(cnt_d,g_cnt_d); SYM(off_m,g_off_m); SYM(off_d,g_off_d);
    SYM(cur_m,g_cur_m); SYM(cur_d,g_cur_d); SYM(csr_src,g_csr_src); SYM(csr_dst,g_csr_dst);

    // allow 74KB dynamic smem for the GEMM variants
    cudaFuncSetAttribute(mma_gemm<true ,false,true ,true >, cudaFuncAttributeMaxDynamicSharedMemorySize, GEMM_SMEM_BYTES);
    cudaFuncSetAttribute(mma_gemm<true ,true ,false,true >, cudaFuncAttributeMaxDynamicSharedMemorySize, GEMM_SMEM_BYTES);
    cudaFuncSetAttribute(mma_gemm<false,false,false,false>, cudaFuncAttributeMaxDynamicSharedMemorySize, GEMM_SMEM_BYTES);
    cudaFuncSetAttribute(mma_gemm<true ,false,false,false>, cudaFuncAttributeMaxDynamicSharedMemorySize, GEMM_SMEM_BYTES);

    // 0) CSR build (independent of GEMMs)
    cudaMemsetAsync(cnt_m, 0, NM * sizeof(int), 0);
    cudaMemsetAsync(cnt_d, 0, ND * sizeof(int), 0);
    count_edges_kernel<<<(NE + 255) / 256, 256>>>(esrc, edst, cnt_m, cnt_d, NE);
    exscan_kernel<<<1, 1024>>>(cnt_d, off_d, ND);
    exscan_kernel<<<1, 1024>>>(cnt_m, off_m, NM);
    cudaMemcpyAsync(cur_d, off_d, ND * sizeof(int), cudaMemcpyDeviceToDevice, 0);
    cudaMemcpyAsync(cur_m, off_m, NM * sizeof(int), cudaMemcpyDeviceToDevice, 0);
    fill_csr_kernel<<<(NE + 255) / 256, 256>>>(esrc, edst, cur_m, cur_d, csr_src, csr_dst, NE);

    // 1) splits: features + all weights
    auto split = [&](const float* x, bf16* h, bf16* l, int n){
        int n4 = n / 4;
        split_kernel<<<(n4 + 255) / 256, 256>>>(x, h, l, n4);
    };
    split(mf, mfh, mfl, NM*FIN);
    split(df, dfh, dfl, ND*FIN);
    split(Wm, wmh, wml, FIN*HD);
    split(Wd, wdh, wdl, FIN*HD);
    split(W1mdl, w1mdlh, w1mdll, HD*H1);
    split(W1mdr, w1mdrh, w1mdrl, HD*H1);
    split(W1dml, w1dmlh, w1dmll, HD*H1);
    split(W1dmr, w1dmrh, w1dmrl, HD*H1);
    split(W2mdl, w2mdlh, w2mdll, H1*OD);
    split(W2mdr, w2mdrh, w2mdrl, H1*OD);
    split(W2dml, w2dmlh, w2dmll, H1*OD);
    split(W2dmr, w2dmrh, w2dmrl, H1*OD);

    // 2) encoders: x = feat@W + b + emb[id]  -> split output
    mma_gemm<true,false,true,true><<<gemm_grid(NM, HD), 256, GEMM_SMEM_BYTES>>>(
        mfh, mfl, wmh, wml, FIN, nullptr,nullptr,nullptr,nullptr, 0,
        NM, HD, bm, memb, mid, nullptr, xmh, xml);
    mma_gemm<true,false,true,true><<<gemm_grid(ND, HD), 256, GEMM_SMEM_BYTES>>>(
        dfh, dfl, wdh, wdl, FIN, nullptr,nullptr,nullptr,nullptr, 0,
        ND, HD, bd, demb, did, nullptr, xdh, xdl);

    // 3) layer1 segment means (split -> split)
    seg_mean_split_kernel<HD><<<ND, HD/4>>>(xmh, xml, off_d, csr_src, adh, adl);
    seg_mean_split_kernel<HD><<<NM, HD/4>>>(xdh, xdl, off_m, csr_dst, amh, aml);

    // 4) layer1 K-fused dual GEMMs: h = relu(agg@Wl + b + x@Wr) -> split output
    mma_gemm<true,true,false,true><<<gemm_grid(ND, H1), 256, GEMM_SMEM_BYTES>>>(
        adh, adl, w1mdlh, w1mdll, HD, xdh, xdl, w1mdrh, w1mdrl, HD,
        ND, H1, b1md, nullptr, nullptr, nullptr, hdh, hdl);
    mma_gemm<true,true,false,true><<<gemm_grid(NM, H1), 256, GEMM_SMEM_BYTES>>>(
        amh, aml, w1dmlh, w1dmll, HD, xmh, xml, w1dmrh, w1dmrl, HD,
        NM, H1, b1dm, nullptr, nullptr, nullptr, hmh, hml);

    // 5) layer2: project messages (GEMM before aggregation; mean commutes)
    mma_gemm<false,false,false,false><<<gemm_grid(NM, OD), 256, GEMM_SMEM_BYTES>>>(
        hmh, hml, w2mdlh, w2mdll, H1, nullptr,nullptr,nullptr,nullptr, 0,
        NM, OD, nullptr, nullptr, nullptr, um, nullptr, nullptr);
    mma_gemm<false,false,false,false><<<gemm_grid(ND, OD), 256, GEMM_SMEM_BYTES>>>(
        hdh, hdl, w2dmlh, w2dmll, H1, nullptr,nullptr,nullptr,nullptr, 0,
        ND, OD, nullptr, nullptr, nullptr, ud, nullptr, nullptr);
    // bases: o = h_dst @ Wr + b  (f32, into d_out)
    mma_gemm<true,false,false,false><<<gemm_grid(ND, OD), 256, GEMM_SMEM_BYTES>>>(
        hdh, hdl, w2mdrh, w2mdrl, H1, nullptr,nullptr,nullptr,nullptr, 0,
        ND, OD, b2md, nullptr, nullptr, o_d, nullptr, nullptr);
    mma_gemm<true,false,false,false><<<gemm_grid(NM, OD), 256, GEMM_SMEM_BYTES>>>(
        hmh, hml, w2dmrh, w2dmrl, H1, nullptr,nullptr,nullptr,nullptr, 0,
        NM, OD, b2dm, nullptr, nullptr, o_m, nullptr, nullptr);

    // 6) accumulate segment means of projected messages into outputs
    seg_mean_acc_kernel<OD><<<ND, OD/4>>>(um, off_d, csr_src, o_d);
    seg_mean_acc_kernel<OD><<<NM, OD/4>>>(ud, off_m, csr_dst, o_m);
}

// round 5
// speedup vs baseline: 2.3157x; 1.0337x over previous
#include <cuda_runtime.h>
#include <cuda_bf16.h>
#include <cstdint>

#define NM 20000
#define ND 8000
#define NE 200000
#define FIN 384
#define HD 512
#define H1 512
#define OD 256

typedef __nv_bfloat16 bf16;
typedef __nv_bfloat162 bf162;

// ---------------- scratch (device globals) ----------------
__device__ bf16 g_mfh[NM*FIN], g_mfl[NM*FIN];
__device__ bf16 g_dfh[ND*FIN], g_dfl[ND*FIN];
__device__ bf16 g_xmh[NM*HD],  g_xml[NM*HD];
__device__ bf16 g_xdh[ND*HD],  g_xdl[ND*HD];
__device__ bf16 g_adh[ND*HD],  g_adl[ND*HD];   // agg onto disease (reused layer1+layer2)
__device__ bf16 g_hmh[NM*H1],  g_hml[NM*H1];
__device__ bf16 g_hdh[ND*H1],  g_hdl[ND*H1];
__device__ float g_qd[ND*H1];                  // layer1 dm projected messages (f32)
__device__ float g_base[NM*H1];                // layer1 dm base (f32)
__device__ float g_ud[ND*OD];                  // layer2 dm projected messages (f32)
// weights [K,N] bf16 hi/lo (same layout as f32 input, split only)
__device__ bf16 g_wmh[FIN*HD], g_wml[FIN*HD];
__device__ bf16 g_wdh[FIN*HD], g_wdl[FIN*HD];
__device__ bf16 g_w1mdlh[HD*H1], g_w1mdll[HD*H1];
__device__ bf16 g_w1mdrh[HD*H1], g_w1mdrl[HD*H1];
__device__ bf16 g_w1dmlh[HD*H1], g_w1dmll[HD*H1];
__device__ bf16 g_w1dmrh[HD*H1], g_w1dmrl[HD*H1];
__device__ bf16 g_w2mdlh[H1*OD], g_w2mdll[H1*OD];
__device__ bf16 g_w2mdrh[H1*OD], g_w2mdrl[H1*OD];
__device__ bf16 g_w2dmlh[H1*OD], g_w2dmll[H1*OD];
__device__ bf16 g_w2dmrh[H1*OD], g_w2dmrl[H1*OD];
__device__ int g_cnt_m[NM], g_cnt_d[ND];
__device__ int g_off_m[NM+1], g_off_d[ND+1];
__device__ int g_cur_m[NM], g_cur_d[ND];
__device__ int g_csr_src[NE];  // grouped by disease dst -> mirna src
__device__ int g_csr_dst[NE];  // grouped by mirna src  -> disease dst

// ---------------- PTX helpers ----------------
__device__ __forceinline__ void ldsm_x4(uint32_t& r0,uint32_t& r1,uint32_t& r2,uint32_t& r3,uint32_t a){
    asm volatile("ldmatrix.sync.aligned.m8n8.x4.shared.b16 {%0,%1,%2,%3},[%4];"
                 :"=r"(r0),"=r"(r1),"=r"(r2),"=r"(r3):"r"(a));
}
__device__ __forceinline__ void ldsm_x4t(uint32_t& r0,uint32_t& r1,uint32_t& r2,uint32_t& r3,uint32_t a){
    asm volatile("ldmatrix.sync.aligned.m8n8.x4.trans.shared.b16 {%0,%1,%2,%3},[%4];"
                 :"=r"(r0),"=r"(r1),"=r"(r2),"=r"(r3):"r"(a));
}
__device__ __forceinline__ void mma_bf16(float* c, const uint32_t* a, uint32_t b0, uint32_t b1){
    asm volatile("mma.sync.aligned.m16n8k16.row.col.f32.bf16.bf16.f32 "
        "{%0,%1,%2,%3},{%4,%5,%6,%7},{%8,%9},{%0,%1,%2,%3};"
        :"+f"(c[0]),"+f"(c[1]),"+f"(c[2]),"+f"(c[3])
        :"r"(a[0]),"r"(a[1]),"r"(a[2]),"r"(a[3]),"r"(b0),"r"(b1));
}
__device__ __forceinline__ void cpa16(uint32_t d, const void* s, bool p){
    int sz = p ? 16 : 0;
    asm volatile("cp.async.cg.shared.global [%0],[%1],16,%2;"::"r"(d),"l"(s),"r"(sz));
}

// smem geometry (bf16 elements) — R2 proven
#define SA 40          // A row stride (32 + 8 pad)
#define SB 136         // B row stride (128 + 8 pad)
#define ASZ (128*SA)
#define BSZ (32*SB)
#define STAGE_E (2*ASZ + 2*BSZ)
#define GEMM_SMEM_BYTES (2*STAGE_E*2)

// ---------------- bf16x3 tensor-core GEMM (R2-proven core) ----------------
// C[M,N] = (A1h+A1l)@(B1h+B1l) (+ A2@B2), A [M,K] row-major, B [K,N] row-major
template<bool BIAS,bool RELU,bool GATH,bool SPLIT>
__global__ __launch_bounds__(256,2) void mma_gemm(
    const bf16* __restrict__ A1h, const bf16* __restrict__ A1l,
    const bf16* __restrict__ B1h, const bf16* __restrict__ B1l, int K1,
    const bf16* __restrict__ A2h, const bf16* __restrict__ A2l,
    const bf16* __restrict__ B2h, const bf16* __restrict__ B2l, int K2,
    int M, int N,
    const float* __restrict__ bias, const float* __restrict__ Demb, const int* __restrict__ idx,
    float* __restrict__ C, bf16* __restrict__ Ch, bf16* __restrict__ Cl)
{
    extern __shared__ bf16 smem[];
    uint32_t sbase = (uint32_t)__cvta_generic_to_shared(smem);
    const int tid  = threadIdx.x;
    const int lane = tid & 31;
    const int wid  = tid >> 5;
    const int wm   = (wid & 3) * 32;
    const int wn   = (wid >> 2) * 64;
    const int bm   = blockIdx.y * 128;
    const int bn   = blockIdx.x * 128;
    const int S1 = K1 >> 5, S2 = K2 >> 5, S = S1 + S2;

    float acc[2][8][4];
#pragma unroll
    for (int i=0;i<2;i++)
#pragma unroll
        for (int j=0;j<8;j++)
#pragma unroll
            for (int k=0;k<4;k++) acc[i][j][k] = 0.f;

    auto prefetch = [&](int s){
        const bf16 *Ah,*Al,*Bh,*Bl; int K,k0;
        if (s < S1){ Ah=A1h; Al=A1l; Bh=B1h; Bl=B1l; K=K1; k0=s<<5; }
        else       { Ah=A2h; Al=A2l; Bh=B2h; Bl=B2l; K=K2; k0=(s-S1)<<5; }
        uint32_t sb = sbase + (uint32_t)((s&1)*STAGE_E*2);
        int ar = tid>>2, ac = (tid&3)*8;
#pragma unroll
        for (int i=0;i<2;i++){
            int row = bm + ar + 64*i;
            bool ok = row < M;
            int sr = ok ? row : 0;
            uint32_t d = sb + (uint32_t)(((ar+64*i)*SA + ac)*2);
            cpa16(d,          Ah + (size_t)sr*K + k0 + ac, ok);
            cpa16(d + ASZ*2,  Al + (size_t)sr*K + k0 + ac, ok);
        }
        int bk = tid>>4, bc = (tid&15)*8;
#pragma unroll
        for (int i=0;i<2;i++){
            int k = bk + 16*i;
            uint32_t d = sb + (uint32_t)(((2*ASZ) + k*SB + bc)*2);
            size_t go = (size_t)(k0 + k)*N + bn + bc;
            cpa16(d,          Bh + go, true);
            cpa16(d + BSZ*2,  Bl + go, true);
        }
        asm volatile("cp.async.commit_group;");
    };

    prefetch(0);
    for (int s=0;s<S;s++){
        if (s+1 < S){
            prefetch(s+1);
            asm volatile("cp.async.wait_group 1;");
        } else {
            asm volatile("cp.async.wait_group 0;");
        }
        __syncthreads();
        uint32_t sb = sbase + (uint32_t)((s&1)*STAGE_E*2);
#pragma unroll
        for (int kk=0;kk<2;kk++){
            const int k16 = kk*16;
            const int loff = (lane>>1)&8;
            uint32_t ah[2][4], al[2][4];
#pragma unroll
            for (int mf=0;mf<2;mf++){
                uint32_t a = sb + (uint32_t)((((wm + mf*16 + (lane&15))*SA) + k16 + loff)*2);
                ldsm_x4(ah[mf][0],ah[mf][1],ah[mf][2],ah[mf][3], a);
                ldsm_x4(al[mf][0],al[mf][1],al[mf][2],al[mf][3], a + ASZ*2);
            }
#pragma unroll
            for (int nb=0;nb<4;nb++){
                uint32_t a = sb + (uint32_t)(((2*ASZ) + (k16 + (lane&15))*SB + wn + nb*16 + loff)*2);
                uint32_t bh[4], bl[4];
                ldsm_x4t(bh[0],bh[1],bh[2],bh[3], a);
                ldsm_x4t(bl[0],bl[1],bl[2],bl[3], a + BSZ*2);
#pragma unroll
                for (int h=0;h<2;h++){
#pragma unroll
                    for (int mf=0;mf<2;mf++){
                        float* c = acc[mf][nb*2+h];
                        mma_bf16(c, ah[mf], bh[2*h], bh[2*h+1]);
                        mma_bf16(c, ah[mf], bl[2*h], bl[2*h+1]);
                        mma_bf16(c, al[mf], bh[2*h], bh[2*h+1]);
                    }
                }
            }
        }
        __syncthreads();
    }

    // epilogue
#pragma unroll
    for (int mf=0;mf<2;mf++){
#pragma unroll
        for (int nf=0;nf<8;nf++){
            int col = bn + wn + nf*8 + (lane&3)*2;
#pragma unroll
            for (int half=0;half<2;half++){
                int row = bm + wm + mf*16 + (lane>>2) + half*8;
                if (row >= M) continue;
                float v0 = acc[mf][nf][half*2+0];
                float v1 = acc[mf][nf][half*2+1];
                if (BIAS){ v0 += __ldg(&bias[col]); v1 += __ldg(&bias[col+1]); }
                if (GATH){
                    int g = __ldg(&idx[row]);
                    const float* e = Demb + (size_t)g*N + col;
                    v0 += __ldg(&e[0]); v1 += __ldg(&e[1]);
                }
                if (RELU){ v0 = fmaxf(v0,0.f); v1 = fmaxf(v1,0.f); }
                if (SPLIT){
                    bf16 h0=__float2bfloat16(v0), h1=__float2bfloat16(v1);
                    bf16 l0=__float2bfloat16(v0-__bfloat162float(h0));
                    bf16 l1=__float2bfloat16(v1-__bfloat162float(h1));
                    *(bf162*)(Ch + (size_t)row*N + col) = __halves2bfloat162(h0,h1);
                    *(bf162*)(Cl + (size_t)row*N + col) = __halves2bfloat162(l0,l1);
                } else {
                    float2 o; o.x=v0; o.y=v1;
                    *(float2*)(C + (size_t)row*N + col) = o;
                }
            }
        }
    }
}

// ---------------- batched split fp32 -> (bf16 hi, bf16 lo) ----------------
struct SplitSet { const float* x[4]; bf16* h[4]; bf16* l[4]; int n4[4]; };
__global__ void bsplit_kernel(SplitSet ss)
{
    int z = blockIdx.y;
    const float* X = ss.x[z]; bf16* H = ss.h[z]; bf16* L = ss.l[z];
    int n4 = ss.n4[z];
    int i = blockIdx.x*blockDim.x + threadIdx.x;
    if (i < n4){
        float4 v = ((const float4*)X)[i];
        bf16 h0=__float2bfloat16(v.x), h1=__float2bfloat16(v.y);
        bf16 h2=__float2bfloat16(v.z), h3=__float2bfloat16(v.w);
        bf16 l0=__float2bfloat16(v.x-__bfloat162float(h0));
        bf16 l1=__float2bfloat16(v.y-__bfloat162float(h1));
        bf16 l2=__float2bfloat16(v.z-__bfloat162float(h2));
        bf16 l3=__float2bfloat16(v.w-__bfloat162float(h3));
        ((bf162*)H)[2*i]   = __halves2bfloat162(h0,h1);
        ((bf162*)H)[2*i+1] = __halves2bfloat162(h2,h3);
        ((bf162*)L)[2*i]   = __halves2bfloat162(l0,l1);
        ((bf162*)L)[2*i+1] = __halves2bfloat162(l2,l3);
    }
}

// ---------------- CSR build ----------------
__global__ void zero_kernel(int* a, int na, int* b, int nb)
{
    int i = blockIdx.x*blockDim.x + threadIdx.x;
    if (i < na) a[i] = 0;
    if (i < nb) b[i] = 0;
}

__global__ void count_edges_kernel(const int* __restrict__ src, const int* __restrict__ dst,
                                   int* __restrict__ cm, int* __restrict__ cd, int E)
{
    int i = blockIdx.x * blockDim.x + threadIdx.x;
    if (i < E) {
        atomicAdd(&cd[dst[i]], 1);
        atomicAdd(&cm[src[i]], 1);
    }
}

// dual-array exclusive scan; also initializes cur = off
__global__ void exscan2_kernel(const int* __restrict__ cnt_d, int* __restrict__ off_d, int* __restrict__ cur_d, int n_d,
                               const int* __restrict__ cnt_m, int* __restrict__ off_m, int* __restrict__ cur_m, int n_m)
{
    const int* cnt; int* off; int* cur; int n;
    if (blockIdx.x == 0){ cnt = cnt_d; off = off_d; cur = cur_d; n = n_d; }
    else               { cnt = cnt_m; off = off_m; cur = cur_m; n = n_m; }
    __shared__ int wsum[32];
    int t = threadIdx.x;
    int chunk = (n + 1023) >> 10;
    int s = t * chunk; if (s > n) s = n;
    int e = s + chunk; if (e > n) e = n;
    int sum = 0;
    for (int i = s; i < e; i++) sum += cnt[i];
    int lane = t & 31, w = t >> 5;
    int v = sum;
#pragma unroll
    for (int d = 1; d < 32; d <<= 1){
        int o = __shfl_up_sync(0xFFFFFFFFu, v, d);
        if (lane >= d) v += o;
    }
    if (lane == 31) wsum[w] = v;
    __syncthreads();
    if (w == 0){
        int x = wsum[lane];
#pragma unroll
        for (int d = 1; d < 32; d <<= 1){
            int o = __shfl_up_sync(0xFFFFFFFFu, x, d);
            if (lane >= d) x += o;
        }
        wsum[lane] = x;
    }
    __syncthreads();
    int run = v - sum + (w > 0 ? wsum[w-1] : 0);
    for (int i = s; i < e; i++){
        off[i] = run; cur[i] = run; run += cnt[i];
    }
    if (t == 1023) off[n] = run;
}

__global__ void fill_csr_kernel(const int* __restrict__ src, const int* __restrict__ dst,
                                int* __restrict__ cur_m, int* __restrict__ cur_d,
                                int* __restrict__ csr_src, int* __restrict__ csr_dst, int E)
{
    int i = blockIdx.x * blockDim.x + threadIdx.x;
    if (i < E) {
        int m = src[i], d = dst[i];
        int p = atomicAdd(&cur_d[d], 1);
        csr_src[p] = m;
        int q = atomicAdd(&cur_m[m], 1);
        csr_dst[q] = d;
    }
}

// ---------------- segment mean: split-in -> split-out ----------------
template<int WIDTH>
__global__ void seg_mean_split_kernel(const bf16* __restrict__ Xh, const bf16* __restrict__ Xl,
                                      const int* __restrict__ off, const int* __restrict__ nbr,
                                      bf16* __restrict__ Ch, bf16* __restrict__ Cl)
{
    int row = blockIdx.x;
    int t = threadIdx.x;
    int s = off[row], e = off[row + 1];
    float a0=0.f,a1=0.f,a2=0.f,a3=0.f;
    for (int i = s; i < e; i++){
        int nb = __ldg(&nbr[i]);
        const bf162* ph = (const bf162*)(Xh + (size_t)nb*WIDTH);
        const bf162* pl = (const bf162*)(Xl + (size_t)nb*WIDTH);
        bf162 h0 = __ldg(&ph[2*t]), h1 = __ldg(&ph[2*t+1]);
        bf162 l0 = __ldg(&pl[2*t]), l1 = __ldg(&pl[2*t+1]);
        a0 += __bfloat162float(h0.x) + __bfloat162float(l0.x);
        a1 += __bfloat162float(h0.y) + __bfloat162float(l0.y);
        a2 += __bfloat162float(h1.x) + __bfloat162float(l1.x);
        a3 += __bfloat162float(h1.y) + __bfloat162float(l1.y);
    }
    float inv = (e > s) ? 1.0f/(float)(e - s) : 0.0f;
    a0 *= inv; a1 *= inv; a2 *= inv; a3 *= inv;
    bf16 h0=__float2bfloat16(a0), h1=__float2bfloat16(a1);
    bf16 h2=__float2bfloat16(a2), h3=__float2bfloat16(a3);
    bf16 l0=__float2bfloat16(a0-__bfloat162float(h0));
    bf16 l1=__float2bfloat16(a1-__bfloat162float(h1));
    bf16 l2=__float2bfloat16(a2-__bfloat162float(h2));
    bf16 l3=__float2bfloat16(a3-__bfloat162float(h3));
    bf162* och = (bf162*)(Ch + (size_t)row*WIDTH);
    bf162* ocl = (bf162*)(Cl + (size_t)row*WIDTH);
    och[2*t]   = __halves2bfloat162(h0,h1);
    och[2*t+1] = __halves2bfloat162(h2,h3);
    ocl[2*t]   = __halves2bfloat162(l0,l1);
    ocl[2*t+1] = __halves2bfloat162(l2,l3);
}

// ---------------- seg mean (f32 msgs) + base + relu -> split out ----------------
template<int WIDTH>
__global__ void seg_relu_split_kernel(const float* __restrict__ Q, const float* __restrict__ Base,
                                      const int* __restrict__ off, const int* __restrict__ nbr,
                                      bf16* __restrict__ Ch, bf16* __restrict__ Cl)
{
    int row = blockIdx.x;
    int t = threadIdx.x;
    int s = off[row], e = off[row + 1];
    float4 acc = make_float4(0.f,0.f,0.f,0.f);
    for (int i = s; i < e; i++){
        int nb = __ldg(&nbr[i]);
        float4 v = __ldg((const float4*)(Q + (size_t)nb*WIDTH) + t);
        acc.x += v.x; acc.y += v.y; acc.z += v.z; acc.w += v.w;
    }
    float inv = (e > s) ? 1.0f/(float)(e - s) : 0.0f;
    float4 b = __ldg((const float4*)(Base + (size_t)row*WIDTH) + t);
    float x0 = fmaxf(b.x + acc.x*inv, 0.f);
    float x1 = fmaxf(b.y + acc.y*inv, 0.f);
    float x2 = fmaxf(b.z + acc.z*inv, 0.f);
    float x3 = fmaxf(b.w + acc.w*inv, 0.f);
    bf16 h0=__float2bfloat16(x0), h1=__float2bfloat16(x1);
    bf16 h2=__float2bfloat16(x2), h3=__float2bfloat16(x3);
    bf16 l0=__float2bfloat16(x0-__bfloat162float(h0));
    bf16 l1=__float2bfloat16(x1-__bfloat162float(h1));
    bf16 l2=__float2bfloat16(x2-__bfloat162float(h2));
    bf16 l3=__float2bfloat16(x3-__bfloat162float(h3));
    bf162* och = (bf162*)(Ch + (size_t)row*WIDTH);
    bf162* ocl = (bf162*)(Cl + (size_t)row*WIDTH);
    och[2*t]   = __halves2bfloat162(h0,h1);
    och[2*t+1] = __halves2bfloat162(h2,h3);
    ocl[2*t]   = __halves2bfloat162(l0,l1);
    ocl[2*t+1] = __halves2bfloat162(l2,l3);
}

// ---------------- segment mean: f32-in, accumulate into f32 out ----------------
template <int WIDTH>
__global__ void seg_mean_acc_kernel(const float* __restrict__ X, const int* __restrict__ off,
                                    const int* __restrict__ nbr, float* __restrict__ C)
{
    int row = blockIdx.x;
    int t = threadIdx.x;
    int s = off[row], e = off[row + 1];
    float4 acc = make_float4(0.f, 0.f, 0.f, 0.f);
    for (int i = s; i < e; i++) {
        int nb = __ldg(&nbr[i]);
        float4 v = __ldg((const float4*)(X + (size_t)nb * WIDTH) + t);
        acc.x += v.x; acc.y += v.y; acc.z += v.z; acc.w += v.w;
    }
    float inv = (e > s) ? 1.0f / (float)(e - s) : 0.0f;
    float4* cp = (float4*)(C + (size_t)row * WIDTH) + t;
    float4 o = *cp;
    o.x += acc.x*inv; o.y += acc.y*inv; o.z += acc.z*inv; o.w += acc.w*inv;
    *cp = o;
}

// ---------------- host orchestration ----------------
static inline dim3 gemm_grid(int M, int N) { return dim3(N / 128, (M + 127) / 128); }
#define SYM(p, s) cudaGetSymbolAddress((void**)&(p), s)

extern "C" void kernel_launch(void* const* d_in, const int* in_sizes, int n_in,
                              void* d_out, int out_size)
{
    const float* mf   = (const float*)d_in[0];
    const float* df   = (const float*)d_in[1];
    const int*   mid  = (const int*)d_in[2];
    const int*   did  = (const int*)d_in[3];
    const int*   esrc = (const int*)d_in[4];
    const int*   edst = (const int*)d_in[5];
    const float* Wm   = (const float*)d_in[6];
    const float* bm   = (const float*)d_in[7];
    const float* Wd   = (const float*)d_in[8];
    const float* bd   = (const float*)d_in[9];
    const float* memb = (const float*)d_in[10];
    const float* demb = (const float*)d_in[11];
    const float* W1mdl = (const float*)d_in[12];
    const float* b1md  = (const float*)d_in[13];
    const float* W1mdr = (const float*)d_in[14];
    const float* W1dml = (const float*)d_in[15];
    const float* b1dm  = (const float*)d_in[16];
    const float* W1dmr = (const float*)d_in[17];
    const float* W2mdl = (const float*)d_in[18];
    const float* b2md  = (const float*)d_in[19];
    const float* W2mdr = (const float*)d_in[20];
    const float* W2dml = (const float*)d_in[21];
    const float* b2dm  = (const float*)d_in[22];
    const float* W2dmr = (const float*)d_in[23];

    float* out = (float*)d_out;
    float* o_m = out;
    float* o_d = out + (size_t)NM * OD;

    bf16 *mfh,*mfl,*dfh,*dfl,*xmh,*xml,*xdh,*xdl,*adh,*adl,*hmh,*hml,*hdh,*hdl;
    bf16 *wmh,*wml,*wdh,*wdl;
    bf16 *w1mdlh,*w1mdll,*w1mdrh,*w1mdrl,*w1dmlh,*w1dmll,*w1dmrh,*w1dmrl;
    bf16 *w2mdlh,*w2mdll,*w2mdrh,*w2mdrl,*w2dmlh,*w2dmll,*w2dmrh,*w2dmrl;
    float *qd,*basem,*ud;
    int *cnt_m,*cnt_d,*off_m,*off_d,*cur_m,*cur_d,*csr_src,*csr_dst;
    SYM(mfh,g_mfh); SYM(mfl,g_mfl); SYM(dfh,g_dfh); SYM(dfl,g_dfl);
    SYM(xmh,g_xmh); SYM(xml,g_xml); SYM(xdh,g_xdh); SYM(xdl,g_xdl);
    SYM(adh,g_adh); SYM(adl,g_adl);
    SYM(hmh,g_hmh); SYM(hml,g_hml); SYM(hdh,g_hdh); SYM(hdl,g_hdl);
    SYM(wmh,g_wmh); SYM(wml,g_wml); SYM(wdh,g_wdh); SYM(wdl,g_wdl);
    SYM(w1mdlh,g_w1mdlh); SYM(w1mdll,g_w1mdll); SYM(w1mdrh,g_w1mdrh); SYM(w1mdrl,g_w1mdrl);
    SYM(w1dmlh,g_w1dmlh); SYM(w1dmll,g_w1dmll); SYM(w1dmrh,g_w1dmrh); SYM(w1dmrl,g_w1dmrl);
    SYM(w2mdlh,g_w2mdlh); SYM(w2mdll,g_w2mdll); SYM(w2mdrh,g_w2mdrh); SYM(w2mdrl,g_w2mdrl);
    SYM(w2dmlh,g_w2dmlh); SYM(w2dmll,g_w2dmll); SYM(w2dmrh,g_w2dmrh); SYM(w2dmrl,g_w2dmrl);
    SYM(qd,g_qd); SYM(basem,g_base); SYM(ud,g_ud);
    SYM(cnt_m,g_cnt_m); SYM(cnt_d,g_cnt_d); SYM(off_m,g_off_m); SYM(off_d,g_off_d);
    SYM(cur_m,g_cur_m); SYM(cur_d,g_cur_d); SYM(csr_src,g_csr_src); SYM(csr_dst,g_csr_dst);

    cudaFuncSetAttribute(mma_gemm<true ,false,true ,true >, cudaFuncAttributeMaxDynamicSharedMemorySize, GEMM_SMEM_BYTES);
    cudaFuncSetAttribute(mma_gemm<true ,true ,false,true >, cudaFuncAttributeMaxDynamicSharedMemorySize, GEMM_SMEM_BYTES);
    cudaFuncSetAttribute(mma_gemm<false,false,false,false>, cudaFuncAttributeMaxDynamicSharedMemorySize, GEMM_SMEM_BYTES);
    cudaFuncSetAttribute(mma_gemm<true ,false,false,false>, cudaFuncAttributeMaxDynamicSharedMemorySize, GEMM_SMEM_BYTES);

    // 0) CSR build
    zero_kernel<<<(NM + 255)/256, 256>>>(cnt_m, NM, cnt_d, ND);
    count_edges_kernel<<<(NE + 255) / 256, 256>>>(esrc, edst, cnt_m, cnt_d, NE);
    exscan2_kernel<<<2, 1024>>>(cnt_d, off_d, cur_d, ND, cnt_m, off_m, cur_m, NM);
    fill_csr_kernel<<<(NE + 255) / 256, 256>>>(esrc, edst, cur_m, cur_d, csr_src, csr_dst, NE);

    // 1) splits: features + encoder weights (one launch), then layer weights (two launches)
    {
        SplitSet s1;
        s1.x[0]=mf; s1.h[0]=mfh; s1.l[0]=mfl; s1.n4[0]=NM*FIN/4;
        s1.x[1]=df; s1.h[1]=dfh; s1.l[1]=dfl; s1.n4[1]=ND*FIN/4;
        s1.x[2]=Wm; s1.h[2]=wmh; s1.l[2]=wml; s1.n4[2]=FIN*HD/4;
        s1.x[3]=Wd; s1.h[3]=wdh; s1.l[3]=wdl; s1.n4[3]=FIN*HD/4;
        int mx = NM*FIN/4;
        bsplit_kernel<<<dim3((mx + 255)/256, 4), 256>>>(s1);

        SplitSet s2;
        s2.x[0]=W1mdl; s2.h[0]=w1mdlh; s2.l[0]=w1mdll; s2.n4[0]=HD*H1/4;
        s2.x[1]=W1mdr; s2.h[1]=w1mdrh; s2.l[1]=w1mdrl; s2.n4[1]=HD*H1/4;
        s2.x[2]=W1dml; s2.h[2]=w1dmlh; s2.l[2]=w1dmll; s2.n4[2]=HD*H1/4;
        s2.x[3]=W1dmr; s2.h[3]=w1dmrh; s2.l[3]=w1dmrl; s2.n4[3]=HD*H1/4;
        bsplit_kernel<<<dim3((HD*H1/4 + 255)/256, 4), 256>>>(s2);

        SplitSet s3;
        s3.x[0]=W2mdl; s3.h[0]=w2mdlh; s3.l[0]=w2mdll; s3.n4[0]=H1*OD/4;
        s3.x[1]=W2mdr; s3.h[1]=w2mdrh; s3.l[1]=w2mdrl; s3.n4[1]=H1*OD/4;
        s3.x[2]=W2dml; s3.h[2]=w2dmlh; s3.l[2]=w2dmll; s3.n4[2]=H1*OD/4;
        s3.x[3]=W2dmr; s3.h[3]=w2dmrh; s3.l[3]=w2dmrl; s3.n4[3]=H1*OD/4;
        bsplit_kernel<<<dim3((H1*OD/4 + 255)/256, 4), 256>>>(s3);
    }

    // 2) encoders: x = feat@W + b + emb[id] -> split
    mma_gemm<true,false,true,true><<<gemm_grid(NM, HD), 256, GEMM_SMEM_BYTES>>>(
        mfh, mfl, wmh, wml, FIN, nullptr,nullptr,nullptr,nullptr, 0,
        NM, HD, bm, memb, mid, nullptr, xmh, xml);
    mma_gemm<true,false,true,true><<<gemm_grid(ND, HD), 256, GEMM_SMEM_BYTES>>>(
        dfh, dfl, wdh, wdl, FIN, nullptr,nullptr,nullptr,nullptr, 0,
        ND, HD, bd, demb, did, nullptr, xdh, xdl);

    // 3) layer1 md (agg-first, dst=disease smaller): agg_d then dual-K GEMM -> h_d
    seg_mean_split_kernel<HD><<<ND, HD/4>>>(xmh, xml, off_d, csr_src, adh, adl);
    mma_gemm<true,true,false,true><<<gemm_grid(ND, H1), 256, GEMM_SMEM_BYTES>>>(
        adh, adl, w1mdlh, w1mdll, HD, xdh, xdl, w1mdrh, w1mdrl, HD,
        ND, H1, b1md, nullptr, nullptr, nullptr, hdh, hdl);

    // 4) layer1 dm (project-first, src=disease smaller):
    //    q_d = x_d @ W1dml (f32); base_m = x_m @ W1dmr + b (f32); h_m = relu(base + mean(q_d))
    mma_gemm<false,false,false,false><<<gemm_grid(ND, H1), 256, GEMM_SMEM_BYTES>>>(
        xdh, xdl, w1dmlh, w1dmll, HD, nullptr,nullptr,nullptr,nullptr, 0,
        ND, H1, nullptr, nullptr, nullptr, qd, nullptr, nullptr);
    mma_gemm<true,false,false,false><<<gemm_grid(NM, H1), 256, GEMM_SMEM_BYTES>>>(
        xmh, xml, w1dmrh, w1dmrl, HD, nullptr,nullptr,nullptr,nullptr, 0,
        NM, H1, b1dm, nullptr, nullptr, basem, nullptr, nullptr);
    seg_relu_split_kernel<H1><<<NM, H1/4>>>(qd, basem, off_m, csr_dst, hmh, hml);

    // 5) layer2 md (agg-first): agg h_m onto diseases, single dual-K GEMM -> o_d
    seg_mean_split_kernel<H1><<<ND, H1/4>>>(hmh, hml, off_d, csr_src, adh, adl);
    mma_gemm<true,false,false,false><<<gemm_grid(ND, OD), 256, GEMM_SMEM_BYTES>>>(
        adh, adl, w2mdlh, w2mdll, H1, hdh, hdl, w2mdrh, w2mdrl, H1,
        ND, OD, b2md, nullptr, nullptr, o_d, nullptr, nullptr);

    // 6) layer2 dm (project-first): ud = h_d @ W2dml; o_m = h_m @ W2dmr + b; o_m += mean(ud)
    mma_gemm<false,false,false,false><<<gemm_grid(ND, OD), 256, GEMM_SMEM_BYTES>>>(
        hdh, hdl, w2dmlh, w2dmll, H1, nullptr,nullptr,nullptr,nullptr, 0,
        ND, OD, nullptr, nullptr, nullptr, ud, nullptr, nullptr);
    mma_gemm<true,false,false,false><<<gemm_grid(NM, OD), 256, GEMM_SMEM_BYTES>>>(
        hmh, hml, w2dmrh, w2dmrl, H1, nullptr,nullptr,nullptr,nullptr, 0,
        NM, OD, b2dm, nullptr, nullptr, o_m, nullptr, nullptr);
    seg_mean_acc_kernel<OD><<<NM, OD/4>>>(ud, off_m, csr_dst, o_m);
}

// round 6
// speedup vs baseline: 2.5545x; 1.1031x over previous
#include <cuda_runtime.h>
#include <cuda_bf16.h>
#include <cstdint>

#define NM 20000
#define ND 8000
#define NE 200000
#define FIN 384
#define HD 512
#define H1 512
#define OD 256

typedef __nv_bfloat16 bf16;
typedef __nv_bfloat162 bf162;

// ---------------- scratch (device globals) ----------------
__device__ bf16 g_mfh[NM*FIN], g_mfl[NM*FIN];
__device__ bf16 g_dfh[ND*FIN], g_dfl[ND*FIN];
__device__ bf16 g_xmh[NM*HD],  g_xml[NM*HD];
__device__ bf16 g_xdh[ND*HD],  g_xdl[ND*HD];
__device__ bf16 g_adh[ND*HD],  g_adl[ND*HD];
__device__ bf16 g_hmh[NM*H1],  g_hml[NM*H1];
__device__ bf16 g_hdh[ND*H1],  g_hdl[ND*H1];
__device__ float g_qd[ND*H1];
__device__ float g_base[NM*H1];
__device__ float g_ud[ND*OD];
__device__ bf16 g_wmh[FIN*HD], g_wml[FIN*HD];
__device__ bf16 g_wdh[FIN*HD], g_wdl[FIN*HD];
__device__ bf16 g_w1mdlh[HD*H1], g_w1mdll[HD*H1];
__device__ bf16 g_w1mdrh[HD*H1], g_w1mdrl[HD*H1];
__device__ bf16 g_w1dmlh[HD*H1], g_w1dmll[HD*H1];
__device__ bf16 g_w1dmrh[HD*H1], g_w1dmrl[HD*H1];
__device__ bf16 g_w2mdlh[H1*OD], g_w2mdll[H1*OD];
__device__ bf16 g_w2mdrh[H1*OD], g_w2mdrl[H1*OD];
__device__ bf16 g_w2dmlh[H1*OD], g_w2dmll[H1*OD];
__device__ bf16 g_w2dmrh[H1*OD], g_w2dmrl[H1*OD];
__device__ int g_cnt_m[NM], g_cnt_d[ND];
__device__ int g_off_m[NM+1], g_off_d[ND+1];
__device__ int g_cur_m[NM], g_cur_d[ND];
__device__ int g_csr_src[NE];
__device__ int g_csr_dst[NE];

// ---------------- PTX helpers ----------------
__device__ __forceinline__ void ldsm_x4(uint32_t& r0,uint32_t& r1,uint32_t& r2,uint32_t& r3,uint32_t a){
    asm volatile("ldmatrix.sync.aligned.m8n8.x4.shared.b16 {%0,%1,%2,%3},[%4];"
                 :"=r"(r0),"=r"(r1),"=r"(r2),"=r"(r3):"r"(a));
}
__device__ __forceinline__ void ldsm_x4t(uint32_t& r0,uint32_t& r1,uint32_t& r2,uint32_t& r3,uint32_t a){
    asm volatile("ldmatrix.sync.aligned.m8n8.x4.trans.shared.b16 {%0,%1,%2,%3},[%4];"
                 :"=r"(r0),"=r"(r1),"=r"(r2),"=r"(r3):"r"(a));
}
__device__ __forceinline__ void mma_bf16(float* c, const uint32_t* a, uint32_t b0, uint32_t b1){
    asm volatile("mma.sync.aligned.m16n8k16.row.col.f32.bf16.bf16.f32 "
        "{%0,%1,%2,%3},{%4,%5,%6,%7},{%8,%9},{%0,%1,%2,%3};"
        :"+f"(c[0]),"+f"(c[1]),"+f"(c[2]),"+f"(c[3])
        :"r"(a[0]),"r"(a[1]),"r"(a[2]),"r"(a[3]),"r"(b0),"r"(b1));
}
__device__ __forceinline__ void cpa16(uint32_t d, const void* s, bool p){
    int sz = p ? 16 : 0;
    asm volatile("cp.async.cg.shared.global [%0],[%1],16,%2;"::"r"(d),"l"(s),"r"(sz));
}

// smem geometry (bf16 elements) — R2 proven
#define SA 40
#define SB 136
#define ASZ (128*SA)
#define BSZ (32*SB)
#define STAGE_E (2*ASZ + 2*BSZ)
#define GEMM_SMEM_BYTES (2*STAGE_E*2)

// flags
#define F_BIAS  1
#define F_RELU  2
#define F_GATH  4
#define F_SPLIT 8

struct GemmDesc {
    const bf16 *A1h,*A1l,*B1h,*B1l;
    const bf16 *A2h,*A2l,*B2h,*B2l;
    int K1, K2, M, N;
    const float *bias, *Demb; const int* idx;
    float* C; bf16 *Ch, *Cl;
    int flags;
    int start, tx;   // first linear tile index; tiles along N
};
struct GemmBatch { GemmDesc g[3]; int n; };

// ---------------- batched bf16x3 tensor-core GEMM (R2-proven core) ----------------
__global__ __launch_bounds__(256,2) void mma_gemm_batched(GemmBatch gb)
{
    extern __shared__ bf16 smem[];
    uint32_t sbase = (uint32_t)__cvta_generic_to_shared(smem);
    const int tid  = threadIdx.x;
    const int lane = tid & 31;
    const int wid  = tid >> 5;
    const int wm   = (wid & 3) * 32;
    const int wn   = (wid >> 2) * 64;

    int gi = 0;
    if (gb.n > 1 && (int)blockIdx.x >= gb.g[1].start) gi = 1;
    if (gb.n > 2 && (int)blockIdx.x >= gb.g[2].start) gi = 2;
    const GemmDesc d = gb.g[gi];

    const int rel = blockIdx.x - d.start;
    const int bn  = (rel % d.tx) * 128;
    const int bm  = (rel / d.tx) * 128;
    const int M = d.M, N = d.N;
    const int S1 = d.K1 >> 5, S2 = d.K2 >> 5, S = S1 + S2;

    float acc[2][8][4];
#pragma unroll
    for (int i=0;i<2;i++)
#pragma unroll
        for (int j=0;j<8;j++)
#pragma unroll
            for (int k=0;k<4;k++) acc[i][j][k] = 0.f;

    auto prefetch = [&](int s){
        const bf16 *Ah,*Al,*Bh,*Bl; int K,k0;
        if (s < S1){ Ah=d.A1h; Al=d.A1l; Bh=d.B1h; Bl=d.B1l; K=d.K1; k0=s<<5; }
        else       { Ah=d.A2h; Al=d.A2l; Bh=d.B2h; Bl=d.B2l; K=d.K2; k0=(s-S1)<<5; }
        uint32_t sb = sbase + (uint32_t)((s&1)*STAGE_E*2);
        int ar = tid>>2, ac = (tid&3)*8;
#pragma unroll
        for (int i=0;i<2;i++){
            int row = bm + ar + 64*i;
            bool ok = row < M;
            int sr = ok ? row : 0;
            uint32_t dd = sb + (uint32_t)(((ar+64*i)*SA + ac)*2);
            cpa16(dd,          Ah + (size_t)sr*K + k0 + ac, ok);
            cpa16(dd + ASZ*2,  Al + (size_t)sr*K + k0 + ac, ok);
        }
        int bk = tid>>4, bc = (tid&15)*8;
#pragma unroll
        for (int i=0;i<2;i++){
            int k = bk + 16*i;
            uint32_t dd = sb + (uint32_t)(((2*ASZ) + k*SB + bc)*2);
            size_t go = (size_t)(k0 + k)*N + bn + bc;
            cpa16(dd,          Bh + go, true);
            cpa16(dd + BSZ*2,  Bl + go, true);
        }
        asm volatile("cp.async.commit_group;");
    };

    prefetch(0);
    for (int s=0;s<S;s++){
        if (s+1 < S){
            prefetch(s+1);
            asm volatile("cp.async.wait_group 1;");
        } else {
            asm volatile("cp.async.wait_group 0;");
        }
        __syncthreads();
        uint32_t sb = sbase + (uint32_t)((s&1)*STAGE_E*2);
#pragma unroll
        for (int kk=0;kk<2;kk++){
            const int k16 = kk*16;
            const int loff = (lane>>1)&8;
            uint32_t ah[2][4], al[2][4];
#pragma unroll
            for (int mf=0;mf<2;mf++){
                uint32_t a = sb + (uint32_t)((((wm + mf*16 + (lane&15))*SA) + k16 + loff)*2);
                ldsm_x4(ah[mf][0],ah[mf][1],ah[mf][2],ah[mf][3], a);
                ldsm_x4(al[mf][0],al[mf][1],al[mf][2],al[mf][3], a + ASZ*2);
            }
#pragma unroll
            for (int nb=0;nb<4;nb++){
                uint32_t a = sb + (uint32_t)(((2*ASZ) + (k16 + (lane&15))*SB + wn + nb*16 + loff)*2);
                uint32_t bh[4], bl[4];
                ldsm_x4t(bh[0],bh[1],bh[2],bh[3], a);
                ldsm_x4t(bl[0],bl[1],bl[2],bl[3], a + BSZ*2);
#pragma unroll
                for (int h=0;h<2;h++){
#pragma unroll
                    for (int mf=0;mf<2;mf++){
                        float* c = acc[mf][nb*2+h];
                        mma_bf16(c, ah[mf], bh[2*h], bh[2*h+1]);
                        mma_bf16(c, ah[mf], bl[2*h], bl[2*h+1]);
                        mma_bf16(c, al[mf], bh[2*h], bh[2*h+1]);
                    }
                }
            }
        }
        __syncthreads();
    }

    // epilogue (flags uniform per block)
    const int fl = d.flags;
#pragma unroll
    for (int mf=0;mf<2;mf++){
#pragma unroll
        for (int nf=0;nf<8;nf++){
            int col = bn + wn + nf*8 + (lane&3)*2;
#pragma unroll
            for (int half=0;half<2;half++){
                int row = bm + wm + mf*16 + (lane>>2) + half*8;
                if (row >= M) continue;
                float v0 = acc[mf][nf][half*2+0];
                float v1 = acc[mf][nf][half*2+1];
                if (fl & F_BIAS){ v0 += __ldg(&d.bias[col]); v1 += __ldg(&d.bias[col+1]); }
                if (fl & F_GATH){
                    int g = __ldg(&d.idx[row]);
                    const float* e = d.Demb + (size_t)g*N + col;
                    v0 += __ldg(&e[0]); v1 += __ldg(&e[1]);
                }
                if (fl & F_RELU){ v0 = fmaxf(v0,0.f); v1 = fmaxf(v1,0.f); }
                if (fl & F_SPLIT){
                    bf16 h0=__float2bfloat16(v0), h1=__float2bfloat16(v1);
                    bf16 l0=__float2bfloat16(v0-__bfloat162float(h0));
                    bf16 l1=__float2bfloat16(v1-__bfloat162float(h1));
                    *(bf162*)(d.Ch + (size_t)row*N + col) = __halves2bfloat162(h0,h1);
                    *(bf162*)(d.Cl + (size_t)row*N + col) = __halves2bfloat162(l0,l1);
                } else {
                    float2 o; o.x=v0; o.y=v1;
                    *(float2*)(d.C + (size_t)row*N + col) = o;
                }
            }
        }
    }
}

// ---------------- batched split fp32 -> (bf16 hi, bf16 lo) ----------------
struct SplitSet { const float* x[4]; bf16* h[4]; bf16* l[4]; int n4[4]; };
__global__ void bsplit_kernel(SplitSet ss)
{
    int z = blockIdx.y;
    const float* X = ss.x[z]; bf16* H = ss.h[z]; bf16* L = ss.l[z];
    int n4 = ss.n4[z];
    int i = blockIdx.x*blockDim.x + threadIdx.x;
    if (i < n4){
        float4 v = ((const float4*)X)[i];
        bf16 h0=__float2bfloat16(v.x), h1=__float2bfloat16(v.y);
        bf16 h2=__float2bfloat16(v.z), h3=__float2bfloat16(v.w);
        bf16 l0=__float2bfloat16(v.x-__bfloat162float(h0));
        bf16 l1=__float2bfloat16(v.y-__bfloat162float(h1));
        bf16 l2=__float2bfloat16(v.z-__bfloat162float(h2));
        bf16 l3=__float2bfloat16(v.w-__bfloat162float(h3));
        ((bf162*)H)[2*i]   = __halves2bfloat162(h0,h1);
        ((bf162*)H)[2*i+1] = __halves2bfloat162(h2,h3);
        ((bf162*)L)[2*i]   = __halves2bfloat162(l0,l1);
        ((bf162*)L)[2*i+1] = __halves2bfloat162(l2,l3);
    }
}

// ---------------- CSR build ----------------
__global__ void zero_kernel(int* a, int na, int* b, int nb)
{
    int i = blockIdx.x*blockDim.x + threadIdx.x;
    if (i < na) a[i] = 0;
    if (i < nb) b[i] = 0;
}

__global__ void count_edges_kernel(const int* __restrict__ src, const int* __restrict__ dst,
                                   int* __restrict__ cm, int* __restrict__ cd, int E)
{
    int i = blockIdx.x * blockDim.x + threadIdx.x;
    if (i < E) {
        atomicAdd(&cd[dst[i]], 1);
        atomicAdd(&cm[src[i]], 1);
    }
}

__global__ void exscan2_kernel(const int* __restrict__ cnt_d, int* __restrict__ off_d, int* __restrict__ cur_d, int n_d,
                               const int* __restrict__ cnt_m, int* __restrict__ off_m, int* __restrict__ cur_m, int n_m)
{
    const int* cnt; int* off; int* cur; int n;
    if (blockIdx.x == 0){ cnt = cnt_d; off = off_d; cur = cur_d; n = n_d; }
    else               { cnt = cnt_m; off = off_m; cur = cur_m; n = n_m; }
    __shared__ int wsum[32];
    int t = threadIdx.x;
    int chunk = (n + 1023) >> 10;
    int s = t * chunk; if (s > n) s = n;
    int e = s + chunk; if (e > n) e = n;
    int sum = 0;
    for (int i = s; i < e; i++) sum += cnt[i];
    int lane = t & 31, w = t >> 5;
    int v = sum;
#pragma unroll
    for (int dd = 1; dd < 32; dd <<= 1){
        int o = __shfl_up_sync(0xFFFFFFFFu, v, dd);
        if (lane >= dd) v += o;
    }
    if (lane == 31) wsum[w] = v;
    __syncthreads();
    if (w == 0){
        int x = wsum[lane];
#pragma unroll
        for (int dd = 1; dd < 32; dd <<= 1){
            int o = __shfl_up_sync(0xFFFFFFFFu, x, dd);
            if (lane >= dd) x += o;
        }
        wsum[lane] = x;
    }
    __syncthreads();
    int run = v - sum + (w > 0 ? wsum[w-1] : 0);
    for (int i = s; i < e; i++){
        off[i] = run; cur[i] = run; run += cnt[i];
    }
    if (t == 1023) off[n] = run;
}

__global__ void fill_csr_kernel(const int* __restrict__ src, const int* __restrict__ dst,
                                int* __restrict__ cur_m, int* __restrict__ cur_d,
                                int* __restrict__ csr_src, int* __restrict__ csr_dst, int E)
{
    int i = blockIdx.x * blockDim.x + threadIdx.x;
    if (i < E) {
        int m = src[i], d = dst[i];
        int p = atomicAdd(&cur_d[d], 1);
        csr_src[p] = m;
        int q = atomicAdd(&cur_m[m], 1);
        csr_dst[q] = d;
    }
}

// ---------------- segment mean: split-in -> split-out ----------------
template<int WIDTH>
__global__ void seg_mean_split_kernel(const bf16* __restrict__ Xh, const bf16* __restrict__ Xl,
                                      const int* __restrict__ off, const int* __restrict__ nbr,
                                      bf16* __restrict__ Ch, bf16* __restrict__ Cl)
{
    int row = blockIdx.x;
    int t = threadIdx.x;
    int s = off[row], e = off[row + 1];
    float a0=0.f,a1=0.f,a2=0.f,a3=0.f;
    for (int i = s; i < e; i++){
        int nb = __ldg(&nbr[i]);
        const bf162* ph = (const bf162*)(Xh + (size_t)nb*WIDTH);
        const bf162* pl = (const bf162*)(Xl + (size_t)nb*WIDTH);
        bf162 h0 = __ldg(&ph[2*t]), h1 = __ldg(&ph[2*t+1]);
        bf162 l0 = __ldg(&pl[2*t]), l1 = __ldg(&pl[2*t+1]);
        a0 += __bfloat162float(h0.x) + __bfloat162float(l0.x);
        a1 += __bfloat162float(h0.y) + __bfloat162float(l0.y);
        a2 += __bfloat162float(h1.x) + __bfloat162float(l1.x);
        a3 += __bfloat162float(h1.y) + __bfloat162float(l1.y);
    }
    float inv = (e > s) ? 1.0f/(float)(e - s) : 0.0f;
    a0 *= inv; a1 *= inv; a2 *= inv; a3 *= inv;
    bf16 h0=__float2bfloat16(a0), h1=__float2bfloat16(a1);
    bf16 h2=__float2bfloat16(a2), h3=__float2bfloat16(a3);
    bf16 l0=__float2bfloat16(a0-__bfloat162float(h0));
    bf16 l1=__float2bfloat16(a1-__bfloat162float(h1));
    bf16 l2=__float2bfloat16(a2-__bfloat162float(h2));
    bf16 l3=__float2bfloat16(a3-__bfloat162float(h3));
    bf162* och = (bf162*)(Ch + (size_t)row*WIDTH);
    bf162* ocl = (bf162*)(Cl + (size_t)row*WIDTH);
    och[2*t]   = __halves2bfloat162(h0,h1);
    och[2*t+1] = __halves2bfloat162(h2,h3);
    ocl[2*t]   = __halves2bfloat162(l0,l1);
    ocl[2*t+1] = __halves2bfloat162(l2,l3);
}

// ---------------- seg mean (f32 msgs) + base + relu -> split out ----------------
template<int WIDTH>
__global__ void seg_relu_split_kernel(const float* __restrict__ Q, const float* __restrict__ Base,
                                      const int* __restrict__ off, const int* __restrict__ nbr,
                                      bf16* __restrict__ Ch, bf16* __restrict__ Cl)
{
    int row = blockIdx.x;
    int t = threadIdx.x;
    int s = off[row], e = off[row + 1];
    float4 acc = make_float4(0.f,0.f,0.f,0.f);
    for (int i = s; i < e; i++){
        int nb = __ldg(&nbr[i]);
        float4 v = __ldg((const float4*)(Q + (size_t)nb*WIDTH) + t);
        acc.x += v.x; acc.y += v.y; acc.z += v.z; acc.w += v.w;
    }
    float inv = (e > s) ? 1.0f/(float)(e - s) : 0.0f;
    float4 b = __ldg((const float4*)(Base + (size_t)row*WIDTH) + t);
    float x0 = fmaxf(b.x + acc.x*inv, 0.f);
    float x1 = fmaxf(b.y + acc.y*inv, 0.f);
    float x2 = fmaxf(b.z + acc.z*inv, 0.f);
    float x3 = fmaxf(b.w + acc.w*inv, 0.f);
    bf16 h0=__float2bfloat16(x0), h1=__float2bfloat16(x1);
    bf16 h2=__float2bfloat16(x2), h3=__float2bfloat16(x3);
    bf16 l0=__float2bfloat16(x0-__bfloat162float(h0));
    bf16 l1=__float2bfloat16(x1-__bfloat162float(h1));
    bf16 l2=__float2bfloat16(x2-__bfloat162float(h2));
    bf16 l3=__float2bfloat16(x3-__bfloat162float(h3));
    bf162* och = (bf162*)(Ch + (size_t)row*WIDTH);
    bf162* ocl = (bf162*)(Cl + (size_t)row*WIDTH);
    och[2*t]   = __halves2bfloat162(h0,h1);
    och[2*t+1] = __halves2bfloat162(h2,h3);
    ocl[2*t]   = __halves2bfloat162(l0,l1);
    ocl[2*t+1] = __halves2bfloat162(l2,l3);
}

// ---------------- segment mean: f32-in, accumulate into f32 out ----------------
template <int WIDTH>
__global__ void seg_mean_acc_kernel(const float* __restrict__ X, const int* __restrict__ off,
                                    const int* __restrict__ nbr, float* __restrict__ C)
{
    int row = blockIdx.x;
    int t = threadIdx.x;
    int s = off[row], e = off[row + 1];
    float4 acc = make_float4(0.f, 0.f, 0.f, 0.f);
    for (int i = s; i < e; i++) {
        int nb = __ldg(&nbr[i]);
        float4 v = __ldg((const float4*)(X + (size_t)nb * WIDTH) + t);
        acc.x += v.x; acc.y += v.y; acc.z += v.z; acc.w += v.w;
    }
    float inv = (e > s) ? 1.0f / (float)(e - s) : 0.0f;
    float4* cp = (float4*)(C + (size_t)row * WIDTH) + t;
    float4 o = *cp;
    o.x += acc.x*inv; o.y += acc.y*inv; o.z += acc.z*inv; o.w += acc.w*inv;
    *cp = o;
}

// ---------------- host orchestration ----------------
#define SYM(p, s) cudaGetSymbolAddress((void**)&(p), s)

static inline GemmDesc mk_desc(
    const bf16* A1h, const bf16* A1l, const bf16* B1h, const bf16* B1l, int K1,
    const bf16* A2h, const bf16* A2l, const bf16* B2h, const bf16* B2l, int K2,
    int M, int N, const float* bias, const float* Demb, const int* idx,
    float* C, bf16* Ch, bf16* Cl, int flags)
{
    GemmDesc d;
    d.A1h=A1h; d.A1l=A1l; d.B1h=B1h; d.B1l=B1l; d.K1=K1;
    d.A2h=A2h; d.A2l=A2l; d.B2h=B2h; d.B2l=B2l; d.K2=K2;
    d.M=M; d.N=N; d.bias=bias; d.Demb=Demb; d.idx=idx;
    d.C=C; d.Ch=Ch; d.Cl=Cl; d.flags=flags;
    d.start=0; d.tx=N/128;
    return d;
}

static inline void launch_batch(GemmDesc* descs, int n)
{
    GemmBatch gb;
    int total = 0;
    for (int i = 0; i < n; i++){
        descs[i].start = total;
        total += descs[i].tx * ((descs[i].M + 127)/128);
        gb.g[i] = descs[i];
    }
    for (int i = n; i < 3; i++){ gb.g[i] = descs[n-1]; gb.g[i].start = 0x7FFFFFFF; }
    gb.n = n;
    mma_gemm_batched<<<total, 256, GEMM_SMEM_BYTES>>>(gb);
}

extern "C" void kernel_launch(void* const* d_in, const int* in_sizes, int n_in,
                              void* d_out, int out_size)
{
    const float* mf   = (const float*)d_in[0];
    const float* df   = (const float*)d_in[1];
    const int*   mid  = (const int*)d_in[2];
    const int*   did  = (const int*)d_in[3];
    const int*   esrc = (const int*)d_in[4];
    const int*   edst = (const int*)d_in[5];
    const float* Wm   = (const float*)d_in[6];
    const float* bm   = (const float*)d_in[7];
    const float* Wd   = (const float*)d_in[8];
    const float* bd   = (const float*)d_in[9];
    const float* memb = (const float*)d_in[10];
    const float* demb = (const float*)d_in[11];
    const float* W1mdl = (const float*)d_in[12];
    const float* b1md  = (const float*)d_in[13];
    const float* W1mdr = (const float*)d_in[14];
    const float* W1dml = (const float*)d_in[15];
    const float* b1dm  = (const float*)d_in[16];
    const float* W1dmr = (const float*)d_in[17];
    const float* W2mdl = (const float*)d_in[18];
    const float* b2md  = (const float*)d_in[19];
    const float* W2mdr = (const float*)d_in[20];
    const float* W2dml = (const float*)d_in[21];
    const float* b2dm  = (const float*)d_in[22];
    const float* W2dmr = (const float*)d_in[23];

    float* out = (float*)d_out;
    float* o_m = out;
    float* o_d = out + (size_t)NM * OD;

    bf16 *mfh,*mfl,*dfh,*dfl,*xmh,*xml,*xdh,*xdl,*adh,*adl,*hmh,*hml,*hdh,*hdl;
    bf16 *wmh,*wml,*wdh,*wdl;
    bf16 *w1mdlh,*w1mdll,*w1mdrh,*w1mdrl,*w1dmlh,*w1dmll,*w1dmrh,*w1dmrl;
    bf16 *w2mdlh,*w2mdll,*w2mdrh,*w2mdrl,*w2dmlh,*w2dmll,*w2dmrh,*w2dmrl;
    float *qd,*basem,*ud;
    int *cnt_m,*cnt_d,*off_m,*off_d,*cur_m,*cur_d,*csr_src,*csr_dst;
    SYM(mfh,g_mfh); SYM(mfl,g_mfl); SYM(dfh,g_dfh); SYM(dfl,g_dfl);
    SYM(xmh,g_xmh); SYM(xml,g_xml); SYM(xdh,g_xdh); SYM(xdl,g_xdl);
    SYM(adh,g_adh); SYM(adl,g_adl);
    SYM(hmh,g_hmh); SYM(hml,g_hml); SYM(hdh,g_hdh); SYM(hdl,g_hdl);
    SYM(wmh,g_wmh); SYM(wml,g_wml); SYM(wdh,g_wdh); SYM(wdl,g_wdl);
    SYM(w1mdlh,g_w1mdlh); SYM(w1mdll,g_w1mdll); SYM(w1mdrh,g_w1mdrh); SYM(w1mdrl,g_w1mdrl);
    SYM(w1dmlh,g_w1dmlh); SYM(w1dmll,g_w1dmll); SYM(w1dmrh,g_w1dmrh); SYM(w1dmrl,g_w1dmrl);
    SYM(w2mdlh,g_w2mdlh); SYM(w2mdll,g_w2mdll); SYM(w2mdrh,g_w2mdrh); SYM(w2mdrl,g_w2mdrl);
    SYM(w2dmlh,g_w2dmlh); SYM(w2dmll,g_w2dmll); SYM(w2dmrh,g_w2dmrh); SYM(w2dmrl,g_w2dmrl);
    SYM(qd,g_qd); SYM(basem,g_base); SYM(ud,g_ud);
    SYM(cnt_m,g_cnt_m); SYM(cnt_d,g_cnt_d); SYM(off_m,g_off_m); SYM(off_d,g_off_d);
    SYM(cur_m,g_cur_m); SYM(cur_d,g_cur_d); SYM(csr_src,g_csr_src); SYM(csr_dst,g_csr_dst);

    cudaFuncSetAttribute(mma_gemm_batched, cudaFuncAttributeMaxDynamicSharedMemorySize, GEMM_SMEM_BYTES);

    // 0) CSR build
    zero_kernel<<<(NM + 255)/256, 256>>>(cnt_m, NM, cnt_d, ND);
    count_edges_kernel<<<(NE + 255) / 256, 256>>>(esrc, edst, cnt_m, cnt_d, NE);
    exscan2_kernel<<<2, 1024>>>(cnt_d, off_d, cur_d, ND, cnt_m, off_m, cur_m, NM);
    fill_csr_kernel<<<(NE + 255) / 256, 256>>>(esrc, edst, cur_m, cur_d, csr_src, csr_dst, NE);

    // 1) splits
    {
        SplitSet s1;
        s1.x[0]=mf; s1.h[0]=mfh; s1.l[0]=mfl; s1.n4[0]=NM*FIN/4;
        s1.x[1]=df; s1.h[1]=dfh; s1.l[1]=dfl; s1.n4[1]=ND*FIN/4;
        s1.x[2]=Wm; s1.h[2]=wmh; s1.l[2]=wml; s1.n4[2]=FIN*HD/4;
        s1.x[3]=Wd; s1.h[3]=wdh; s1.l[3]=wdl; s1.n4[3]=FIN*HD/4;
        int mx = NM*FIN/4;
        bsplit_kernel<<<dim3((mx + 255)/256, 4), 256>>>(s1);

        SplitSet s2;
        s2.x[0]=W1mdl; s2.h[0]=w1mdlh; s2.l[0]=w1mdll; s2.n4[0]=HD*H1/4;
        s2.x[1]=W1mdr; s2.h[1]=w1mdrh; s2.l[1]=w1mdrl; s2.n4[1]=HD*H1/4;
        s2.x[2]=W1dml; s2.h[2]=w1dmlh; s2.l[2]=w1dmll; s2.n4[2]=HD*H1/4;
        s2.x[3]=W1dmr; s2.h[3]=w1dmrh; s2.l[3]=w1dmrl; s2.n4[3]=HD*H1/4;
        bsplit_kernel<<<dim3((HD*H1/4 + 255)/256, 4), 256>>>(s2);

        SplitSet s3;
        s3.x[0]=W2mdl; s3.h[0]=w2mdlh; s3.l[0]=w2mdll; s3.n4[0]=H1*OD/4;
        s3.x[1]=W2mdr; s3.h[1]=w2mdrh; s3.l[1]=w2mdrl; s3.n4[1]=H1*OD/4;
        s3.x[2]=W2dml; s3.h[2]=w2dmlh; s3.l[2]=w2dmll; s3.n4[2]=H1*OD/4;
        s3.x[3]=W2dmr; s3.h[3]=w2dmrh; s3.l[3]=w2dmrl; s3.n4[3]=H1*OD/4;
        bsplit_kernel<<<dim3((H1*OD/4 + 255)/256, 4), 256>>>(s3);
    }

    // 2) Group A: both encoders in one launch
    {
        GemmDesc ds[2] = {
            mk_desc(mfh, mfl, wmh, wml, FIN, 0,0,0,0, 0,
                    NM, HD, bm, memb, mid, nullptr, xmh, xml, F_BIAS|F_GATH|F_SPLIT),
            mk_desc(dfh, dfl, wdh, wdl, FIN, 0,0,0,0, 0,
                    ND, HD, bd, demb, did, nullptr, xdh, xdl, F_BIAS|F_GATH|F_SPLIT)
        };
        launch_batch(ds, 2);
    }

    // 3) layer1 md aggregation
    seg_mean_split_kernel<HD><<<ND, HD/4>>>(xmh, xml, off_d, csr_src, adh, adl);

    // 4) Group B: L1md-dual + qd + base_m in one launch
    {
        GemmDesc ds[3] = {
            mk_desc(adh, adl, w1mdlh, w1mdll, HD, xdh, xdl, w1mdrh, w1mdrl, HD,
                    ND, H1, b1md, nullptr, nullptr, nullptr, hdh, hdl, F_BIAS|F_RELU|F_SPLIT),
            mk_desc(xdh, xdl, w1dmlh, w1dmll, HD, 0,0,0,0, 0,
                    ND, H1, nullptr, nullptr, nullptr, qd, nullptr, nullptr, 0),
            mk_desc(xmh, xml, w1dmrh, w1dmrl, HD, 0,0,0,0, 0,
                    NM, H1, b1dm, nullptr, nullptr, basem, nullptr, nullptr, F_BIAS)
        };
        launch_batch(ds, 3);
    }

    // 5) h_m = relu(base + mean(q_d)); layer2 md aggregation of h_m
    seg_relu_split_kernel<H1><<<NM, H1/4>>>(qd, basem, off_m, csr_dst, hmh, hml);
    seg_mean_split_kernel<H1><<<ND, H1/4>>>(hmh, hml, off_d, csr_src, adh, adl);

    // 6) Group C: L2md-dual + ud + o_m base in one launch
    {
        GemmDesc ds[3] = {
            mk_desc(adh, adl, w2mdlh, w2mdll, H1, hdh, hdl, w2mdrh, w2mdrl, H1,
                    ND, OD, b2md, nullptr, nullptr, o_d, nullptr, nullptr, F_BIAS),
            mk_desc(hdh, hdl, w2dmlh, w2dmll, H1, 0,0,0,0, 0,
                    ND, OD, nullptr, nullptr, nullptr, ud, nullptr, nullptr, 0),
            mk_desc(hmh, hml, w2dmrh, w2dmrl, H1, 0,0,0,0, 0,
                    NM, OD, b2dm, nullptr, nullptr, o_m, nullptr, nullptr, F_BIAS)
        };
        launch_batch(ds, 3);
    }

    // 7) o_m += mean(ud over incident diseases)
    seg_mean_acc_kernel<OD><<<NM, OD/4>>>(ud, off_m, csr_dst, o_m);
}